// round 4
// baseline (speedup 1.0000x reference)
#include <cuda_runtime.h>

#define BB 4
#define CC 64
#define NN 8192
#define KNB 40
#define FFD 256
#define NPTS (BB*NN)

// ---------------- scratch (device globals: no allocations allowed) ----------
__device__ float g_pcd[NPTS*CC];   // (B,N,C) transposed input
__device__ float g_aa [NPTS];      // squared norms
__device__ float g_qp [NPTS*CC];   // pcd @ Wq^T
__device__ float g_kp [NPTS*CC];   // pcd @ Wk^T
__device__ float g_vp [NPTS*CC];   // pcd @ Wv^T
__device__ int   g_idx[NPTS*KNB];  // knn indices
__device__ float g_y1 [NPTS*CC];   // (B,N,C) x + attn_out  (pre-BN1)
__device__ float g_y2 [NPTS*CC];   // (B,N,C) x1 + ff       (pre-BN2)
__device__ float g_part[2*64*128]; // BN partial sums [stage][block][{sum64,sumsq64}]
__device__ float g_scb [2*128];    // BN scale/bias   [stage][{scale64,bias64}]

// ---------------- K1: transpose x (B,C,N) -> pcd (B,N,C) --------------------
__global__ void k_transpose(const float* __restrict__ x){
    __shared__ float t[32][33];
    const int n0 = blockIdx.x*32, c0 = blockIdx.y*32, b = blockIdx.z;
    const float* xb = x + (size_t)b*CC*NN;
    #pragma unroll
    for (int i = threadIdx.y; i < 32; i += 8)
        t[i][threadIdx.x] = xb[(size_t)(c0+i)*NN + n0 + threadIdx.x];
    __syncthreads();
    float* pb = g_pcd + (size_t)b*NN*CC;
    #pragma unroll
    for (int i = threadIdx.y; i < 32; i += 8)
        pb[(size_t)(n0+i)*CC + c0 + threadIdx.x] = t[threadIdx.x][i];
}

// ---------------- K1b: aa[p] = sum_c pcd[p][c]^2 (warp per point) -----------
__global__ void k_aa(){
    const int p    = blockIdx.x*8 + (threadIdx.x>>5);
    const int lane = threadIdx.x & 31;
    const float* r = g_pcd + (size_t)p*CC;
    float a = r[lane]*r[lane] + r[lane+32]*r[lane+32];
    #pragma unroll
    for (int o = 16; o; o >>= 1) a += __shfl_xor_sync(0xffffffffu, a, o);
    if (!lane) g_aa[p] = a;
}

// ---------------- K2: qp/kp/vp = pcd @ W^T (64-pt tiles) ---------------------
__global__ void __launch_bounds__(256) k_proj(const float* __restrict__ Wq,
                                              const float* __restrict__ Wk,
                                              const float* __restrict__ Wv){
    __shared__ float Pt[64*68];   // [k][p]
    __shared__ float Wt[64*68];   // [k][o]
    const int t  = threadIdx.x;
    const int r0 = blockIdx.x*64;
    for (int i = t; i < 64*64; i += 256){
        int p = i>>6, k = i&63;
        Pt[k*68+p] = g_pcd[(size_t)(r0+p)*CC + k];
    }
    const int tp = t & 15, to = t >> 4;
    const float* Ws[3] = {Wq, Wk, Wv};
    float* Os[3];
    Os[0] = g_qp; Os[1] = g_kp; Os[2] = g_vp;
    for (int m = 0; m < 3; m++){
        __syncthreads();
        const float* W = Ws[m];
        for (int i = t; i < 64*64; i += 256){
            int o = i>>6, k = i&63;
            Wt[k*68+o] = W[i];
        }
        __syncthreads();
        float acc[4][4];
        #pragma unroll
        for (int i=0;i<4;i++) { acc[i][0]=0.f; acc[i][1]=0.f; acc[i][2]=0.f; acc[i][3]=0.f; }
        #pragma unroll 8
        for (int kk = 0; kk < 64; kk++){
            float4 a = *(const float4*)&Pt[kk*68 + tp*4];
            float4 w = *(const float4*)&Wt[kk*68 + to*4];
            float av[4] = {a.x,a.y,a.z,a.w};
            float wv[4] = {w.x,w.y,w.z,w.w};
            #pragma unroll
            for (int i=0;i<4;i++)
                #pragma unroll
                for (int j=0;j<4;j++) acc[i][j] += av[i]*wv[j];
        }
        float* O = Os[m];
        #pragma unroll
        for (int i = 0; i < 4; i++){
            float4 v4 = make_float4(acc[i][0], acc[i][1], acc[i][2], acc[i][3]);
            *(float4*)&O[(size_t)(r0 + tp*4 + i)*CC + to*4] = v4;
        }
    }
}

// ---------------- K3: fused KNN (distance GEMM + streaming top-40) ----------
#define KNN_SMEM ((64*132*2 + 128*129 + 128 + 128 + 40*128*2)*4)
__global__ void __launch_bounds__(256,1) k_knn(){
    extern __shared__ float s[];
    float* Qs  = s;                   // [k][q], pitch 132
    float* Cs  = Qs  + 64*132;        // [k][c], pitch 132
    float* pdS = Cs  + 64*132;        // [q][c], pitch 129
    float* aq  = pdS + 128*129;       // 128
    float* ac  = aq  + 128;           // 128
    float* ld  = ac  + 128;           // top-40 pd values, [j*128+q]
    int*   li  = (int*)(ld + 40*128); // top-40 indices
    const int b  = blockIdx.y;
    const int q0 = blockIdx.x*128;
    const int t  = threadIdx.x;
    const float* pb = g_pcd + (size_t)b*NN*CC;
    const float* ab = g_aa + (size_t)b*NN;
    for (int i = t; i < 128*64; i += 256){
        int q = i>>6, k = i&63;
        Qs[k*132+q] = pb[(size_t)(q0+q)*CC + k];
    }
    if (t < 128) aq[t] = ab[q0+t];
    for (int i = t; i < 40*128; i += 256){ ld[i] = -3.4e38f; li[i] = 0; }
    const int tq = t & 15, tc = t >> 4;
    for (int ct = 0; ct < NN/128; ct++){
        __syncthreads();
        const int c0 = ct*128;
        for (int i = t; i < 128*64; i += 256){
            int c = i>>6, k = i&63;
            Cs[k*132+c] = pb[(size_t)(c0+c)*CC + k];
        }
        if (t < 128) ac[t] = ab[c0+t];
        __syncthreads();
        float acc[8][8];
        #pragma unroll
        for (int i=0;i<8;i++)
            #pragma unroll
            for (int j=0;j<8;j++) acc[i][j] = 0.f;
        #pragma unroll 4
        for (int kk = 0; kk < 64; kk++){
            float4 a0 = *(const float4*)&Qs[kk*132 + tq*8];
            float4 a1 = *(const float4*)&Qs[kk*132 + tq*8 + 4];
            float4 b0 = *(const float4*)&Cs[kk*132 + tc*8];
            float4 b1 = *(const float4*)&Cs[kk*132 + tc*8 + 4];
            float av[8] = {a0.x,a0.y,a0.z,a0.w,a1.x,a1.y,a1.z,a1.w};
            float bv[8] = {b0.x,b0.y,b0.z,b0.w,b1.x,b1.y,b1.z,b1.w};
            #pragma unroll
            for (int i=0;i<8;i++)
                #pragma unroll
                for (int j=0;j<8;j++) acc[i][j] += av[i]*bv[j];
        }
        #pragma unroll
        for (int i = 0; i < 8; i++){
            float a_q = aq[tq*8+i];
            #pragma unroll
            for (int j = 0; j < 8; j++)
                pdS[(tq*8+i)*129 + tc*8+j] = 2.f*acc[i][j] - a_q - ac[tc*8+j];
        }
        __syncthreads();
        if (t < 128){
            float vmin = ld[39*128 + t];
            for (int ci = 0; ci < 128; ci++){
                float v = pdS[t*129 + ci];
                if (v <= vmin) continue;            // ties keep lower index (already in list)
                int pos = 39;
                while (pos > 0 && ld[(pos-1)*128 + t] < v){   // strict: stable wrt equal values
                    ld[pos*128 + t] = ld[(pos-1)*128 + t];
                    li[pos*128 + t] = li[(pos-1)*128 + t];
                    pos--;
                }
                ld[pos*128 + t] = v;
                li[pos*128 + t] = c0 + ci;
                vmin = ld[39*128 + t];
            }
        }
    }
    __syncthreads();
    if (t < 128){
        int* dst = g_idx + ((size_t)b*NN + q0 + t)*KNB;
        #pragma unroll
        for (int j = 0; j < KNB; j++) dst[j] = li[j*128 + t];
    }
}

// ---------------- K4: attention via gathered projections (warp / point) -----
__global__ void __launch_bounds__(256) k_attn(const float* __restrict__ x){
    __shared__ float es[8][160];   // [warp][head*40+j]
    __shared__ int   sidx[8][40];
    const int w    = threadIdx.x >> 5;
    const int lane = threadIdx.x & 31;
    const int pg   = blockIdx.x*8 + w;       // global point id
    const int b    = pg >> 13, p = pg & (NN-1);
    const int* ip  = g_idx + (size_t)pg*KNB;
    sidx[w][lane] = ip[lane];
    if (lane < 8) sidx[w][lane+32] = ip[lane+32];
    const float* qrow = g_qp + (size_t)pg*CC;
    const float* kb   = g_kp + (size_t)b*NN*CC;
    const float* vb   = g_vp + (size_t)b*NN*CC;
    const float q0 = qrow[lane]    * 0.25f;   // fold 1/sqrt(D)=1/4
    const float q1 = qrow[lane+32] * 0.25f;
    const float kn0 = kb[(size_t)p*CC + lane];
    const float kn1 = kb[(size_t)p*CC + lane + 32];
    __syncwarp();
    const int hq = lane >> 4;   // 0/1 -> heads (hq, 2+hq)
    for (int j = 0; j < KNB; j++){
        const float* kr = kb + (size_t)sidx[w][j]*CC;
        float p0 = q0*(kr[lane]    - kn0);
        float p1 = q1*(kr[lane+32] - kn1);
        #pragma unroll
        for (int o = 8; o; o >>= 1){
            p0 += __shfl_xor_sync(0xffffffffu, p0, o);
            p1 += __shfl_xor_sync(0xffffffffu, p1, o);
        }
        if ((lane & 15) == 0){
            es[w][hq*40 + j]     = p0;
            es[w][(2+hq)*40 + j] = p1;
        }
    }
    __syncwarp();
    if (lane < 4){
        float m = -3.4e38f;
        for (int j = 0; j < KNB; j++) m = fmaxf(m, es[w][lane*40+j]);
        float ssum = 0.f;
        for (int j = 0; j < KNB; j++){
            float e = __expf(es[w][lane*40+j] - m);
            es[w][lane*40+j] = e;
            ssum += e;
        }
        float inv = 1.f/ssum;
        for (int j = 0; j < KNB; j++) es[w][lane*40+j] *= inv;
    }
    __syncwarp();
    const float vn0 = vb[(size_t)p*CC + lane];
    const float vn1 = vb[(size_t)p*CC + lane + 32];
    float a0 = 0.f, a1 = 0.f;
    for (int j = 0; j < KNB; j++){
        const float* vr = vb + (size_t)sidx[w][j]*CC;
        a0 += es[w][hq*40+j]     * (vr[lane]    - vn0);
        a1 += es[w][(2+hq)*40+j] * (vr[lane+32] - vn1);
    }
    const float* xb = x + (size_t)b*CC*NN;
    g_y1[(size_t)pg*CC + lane]      = a0 + xb[(size_t)lane*NN + p];
    g_y1[(size_t)pg*CC + lane + 32] = a1 + xb[(size_t)(lane+32)*NN + p];
}

// ---------------- K5: BN stats (deterministic two-stage) ---------------------
// 64 blocks x 512 rows each covers NPTS=32768 rows exactly.
__global__ void __launch_bounds__(256) k_stats(int srcsel, int which){
    __shared__ float ssum[256], ssq[256];
    const float* src = srcsel ? g_y2 : g_y1;
    const int t = threadIdx.x;
    const int c = t & 63, rl = t >> 6;
    const int r0 = blockIdx.x*512;
    float s = 0.f, s2 = 0.f;
    for (int r = rl; r < 512; r += 4){
        float v = src[(size_t)(r0+r)*CC + c];
        s += v; s2 += v*v;
    }
    ssum[t] = s; ssq[t] = s2;
    __syncthreads();
    if (t < 64){
        float a = ssum[t]+ssum[t+64]+ssum[t+128]+ssum[t+192];
        float q = ssq [t]+ssq [t+64]+ssq [t+128]+ssq [t+192];
        float* part = g_part + which*8192;
        part[blockIdx.x*128 + t]      = a;
        part[blockIdx.x*128 + 64 + t] = q;
    }
}

__global__ void k_bnfin(int which, const float* __restrict__ gamma,
                        const float* __restrict__ beta){
    const int c = threadIdx.x;   // 64 threads
    const float* part = g_part + which*8192;
    float s = 0.f, s2 = 0.f;
    for (int blk = 0; blk < 64; blk++){
        s  += part[blk*128 + c];
        s2 += part[blk*128 + 64 + c];
    }
    const float inv = 1.f/(float)NPTS;
    float m = s*inv;
    float v = s2*inv - m*m;
    float sc = gamma[c]*rsqrtf(v + 1e-5f);
    g_scb[which*128 + c]      = sc;
    g_scb[which*128 + 64 + c] = beta[c] - m*sc;
}

// ---------------- K6: fused FFN (BN1-apply + W1/lrelu + W2 + residual) ------
#define FFN_SMEM ((64*68 + 64*260 + 256*68 + 256*68)*4)
__global__ void __launch_bounds__(256,1) k_ffn(const float* __restrict__ W1,
                                               const float* __restrict__ W2){
    extern __shared__ float s[];
    float* Xs  = s;               // [c][r]  pitch 68   (x1, post-BN1)
    float* W1t = Xs  + 64*68;     // [c][o]  pitch 260
    float* Hs  = W1t + 64*260;    // [o][r]  pitch 68
    float* W2t = Hs  + 256*68;    // [o][c]  pitch 68
    __shared__ float sc1[64], bs1[64];
    const int t  = threadIdx.x;
    const int r0 = blockIdx.x*64;
    if (t < 64){ sc1[t] = g_scb[t]; bs1[t] = g_scb[64+t]; }
    for (int i = t; i < 256*64; i += 256){           // W1 (o,c) -> W1t[c][o]
        int o = i>>6, c = i&63;
        W1t[c*260 + o] = W1[i];
    }
    for (int i = t; i < 64*256; i += 256){           // W2 (c,o) -> W2t[o][c]
        int c = i>>8, o = i&255;
        W2t[o*68 + c] = W2[i];
    }
    __syncthreads();
    for (int i = t; i < 64*64; i += 256){            // x1 = BN1(y1)
        int r = i>>6, c = i&63;
        Xs[c*68 + r] = g_y1[(size_t)(r0+r)*CC + c]*sc1[c] + bs1[c];
    }
    __syncthreads();
    {   // stage 1: H[o][r] = lrelu( sum_c W1[o][c] * x1[c][r] )
        const int to = t >> 3, tr = t & 7;           // o = to*8.., r = tr*8..
        float acc[8][8];
        #pragma unroll
        for (int i=0;i<8;i++)
            #pragma unroll
            for (int j=0;j<8;j++) acc[i][j] = 0.f;
        #pragma unroll 4
        for (int k = 0; k < 64; k++){
            float4 a0 = *(const float4*)&Xs[k*68 + tr*8];
            float4 a1 = *(const float4*)&Xs[k*68 + tr*8 + 4];
            float4 w0 = *(const float4*)&W1t[k*260 + to*8];
            float4 w1 = *(const float4*)&W1t[k*260 + to*8 + 4];
            float av[8] = {a0.x,a0.y,a0.z,a0.w,a1.x,a1.y,a1.z,a1.w};
            float wv[8] = {w0.x,w0.y,w0.z,w0.w,w1.x,w1.y,w1.z,w1.w};
            #pragma unroll
            for (int oi=0;oi<8;oi++)
                #pragma unroll
                for (int ri=0;ri<8;ri++) acc[oi][ri] += wv[oi]*av[ri];
        }
        #pragma unroll
        for (int oi=0;oi<8;oi++)
            #pragma unroll
            for (int ri=0;ri<8;ri++){
                float h = acc[oi][ri];
                Hs[(to*8+oi)*68 + tr*8+ri] = (h > 0.f) ? h : 0.2f*h;
            }
    }
    __syncthreads();
    {   // stage 2: y2[r][c] = x1[c][r] + sum_o W2[c][o]*H[o][r]
        const int tr2 = t & 15, tc2 = t >> 4;        // r = tr2*4.., c = tc2*4..
        float acc[4][4];
        #pragma unroll
        for (int i=0;i<4;i++){ acc[i][0]=0.f; acc[i][1]=0.f; acc[i][2]=0.f; acc[i][3]=0.f; }
        #pragma unroll 8
        for (int o = 0; o < 256; o++){
            float4 h4 = *(const float4*)&Hs[o*68 + tr2*4];
            float4 w4 = *(const float4*)&W2t[o*68 + tc2*4];
            float hv[4] = {h4.x,h4.y,h4.z,h4.w};
            float wv[4] = {w4.x,w4.y,w4.z,w4.w};
            #pragma unroll
            for (int i=0;i<4;i++)
                #pragma unroll
                for (int j=0;j<4;j++) acc[i][j] += hv[i]*wv[j];
        }
        #pragma unroll
        for (int i = 0; i < 4; i++){
            int r = tr2*4 + i;
            float4 outv;
            outv.x = acc[i][0] + Xs[(tc2*4+0)*68 + r];
            outv.y = acc[i][1] + Xs[(tc2*4+1)*68 + r];
            outv.z = acc[i][2] + Xs[(tc2*4+2)*68 + r];
            outv.w = acc[i][3] + Xs[(tc2*4+3)*68 + r];
            *(float4*)&g_y2[(size_t)(r0+r)*CC + tc2*4] = outv;
        }
    }
}

// ---------------- K8: apply BN2 + transpose to (B,C,N) ----------------------
__global__ void __launch_bounds__(256) k_apply(float* __restrict__ out){
    __shared__ float tile[64][65];
    __shared__ float sc[64], bs[64];
    const int t = threadIdx.x;
    if (t < 64){ sc[t] = g_scb[128 + t]; bs[t] = g_scb[128 + 64 + t]; }
    const int n0 = blockIdx.x*64, b = blockIdx.y;
    __syncthreads();
    for (int i = t; i < 64*64; i += 256){
        int r = i>>6, c = i&63;
        tile[c][r] = g_y2[((size_t)b*NN + n0 + r)*CC + c]*sc[c] + bs[c];
    }
    __syncthreads();
    for (int i = t; i < 64*64; i += 256){
        int c = i>>6, n = i&63;
        out[((size_t)b*CC + c)*NN + n0 + n] = tile[c][n];
    }
}

// ---------------- launch -----------------------------------------------------
extern "C" void kernel_launch(void* const* d_in, const int* in_sizes, int n_in,
                              void* d_out, int out_size){
    const float* x  = (const float*)d_in[0];
    const float* Wq = (const float*)d_in[1];
    const float* Wk = (const float*)d_in[2];
    const float* Wv = (const float*)d_in[3];
    const float* W1 = (const float*)d_in[4];
    const float* W2 = (const float*)d_in[5];
    const float* g1 = (const float*)d_in[6];
    const float* b1 = (const float*)d_in[7];
    const float* g2 = (const float*)d_in[8];
    const float* b2 = (const float*)d_in[9];
    float* out = (float*)d_out;
    (void)in_sizes; (void)n_in; (void)out_size;

    cudaFuncSetAttribute(k_knn, cudaFuncAttributeMaxDynamicSharedMemorySize, KNN_SMEM);
    cudaFuncSetAttribute(k_ffn, cudaFuncAttributeMaxDynamicSharedMemorySize, FFN_SMEM);

    k_transpose<<<dim3(NN/32, CC/32, BB), dim3(32, 8)>>>(x);
    k_aa<<<NPTS/8, 256>>>();
    k_proj<<<NPTS/64, 256>>>(Wq, Wk, Wv);
    k_knn<<<dim3(NN/128, BB), 256, KNN_SMEM>>>();
    k_attn<<<NPTS/8, 256>>>(x);
    k_stats<<<64, 256>>>(0, 0);
    k_bnfin<<<1, 64>>>(0, g1, b1);
    k_ffn<<<NPTS/64, 256, FFN_SMEM>>>(W1, W2);
    k_stats<<<64, 256>>>(1, 1);
    k_bnfin<<<1, 64>>>(1, g2, b2);
    k_apply<<<dim3(NN/64, BB), 256>>>(out);
}

// round 5
// speedup vs baseline: 2.7136x; 2.7136x over previous
#include <cuda_runtime.h>

#define BB 4
#define CC 64
#define NN 8192
#define KNB 40
#define FFD 256
#define NPTS (BB*NN)
#define BCAP 48
#define BPITCH 49

// ---------------- scratch (device globals: no allocations allowed) ----------
__device__ float g_pcd[NPTS*CC];   // (B,N,C) transposed input
__device__ float g_aa [NPTS];      // squared norms
__device__ float g_qp [NPTS*CC];   // pcd @ Wq^T
__device__ float g_kp [NPTS*CC];   // pcd @ Wk^T
__device__ float g_vp [NPTS*CC];   // pcd @ Wv^T
__device__ int   g_idx[NPTS*KNB];  // knn indices
__device__ float g_y1 [NPTS*CC];   // (B,N,C) x + attn_out  (pre-BN1)
__device__ float g_y2 [NPTS*CC];   // (B,N,C) x1 + ff       (pre-BN2)
__device__ float g_part[2*64*128]; // BN partial sums
__device__ float g_scb [2*128];    // BN scale/bias

// ---------------- K1: transpose x (B,C,N) -> pcd (B,N,C) --------------------
__global__ void k_transpose(const float* __restrict__ x){
    __shared__ float t[32][33];
    const int n0 = blockIdx.x*32, c0 = blockIdx.y*32, b = blockIdx.z;
    const float* xb = x + (size_t)b*CC*NN;
    #pragma unroll
    for (int i = threadIdx.y; i < 32; i += 8)
        t[i][threadIdx.x] = xb[(size_t)(c0+i)*NN + n0 + threadIdx.x];
    __syncthreads();
    float* pb = g_pcd + (size_t)b*NN*CC;
    #pragma unroll
    for (int i = threadIdx.y; i < 32; i += 8)
        pb[(size_t)(n0+i)*CC + c0 + threadIdx.x] = t[threadIdx.x][i];
}

// ---------------- K1b: aa[p] = sum_c pcd[p][c]^2 (warp per point) -----------
__global__ void k_aa(){
    const int p    = blockIdx.x*8 + (threadIdx.x>>5);
    const int lane = threadIdx.x & 31;
    const float* r = g_pcd + (size_t)p*CC;
    float a = r[lane]*r[lane] + r[lane+32]*r[lane+32];
    #pragma unroll
    for (int o = 16; o; o >>= 1) a += __shfl_xor_sync(0xffffffffu, a, o);
    if (!lane) g_aa[p] = a;
}

// ---------------- K2: qp/kp/vp = pcd @ W^T (64-pt tiles) ---------------------
__global__ void __launch_bounds__(256) k_proj(const float* __restrict__ Wq,
                                              const float* __restrict__ Wk,
                                              const float* __restrict__ Wv){
    __shared__ float Pt[64*68];   // [k][p]
    __shared__ float Wt[64*68];   // [k][o]
    const int t  = threadIdx.x;
    const int r0 = blockIdx.x*64;
    for (int i = t; i < 64*64; i += 256){
        int p = i>>6, k = i&63;
        Pt[k*68+p] = g_pcd[(size_t)(r0+p)*CC + k];
    }
    const int tp = t & 15, to = t >> 4;
    const float* Ws[3] = {Wq, Wk, Wv};
    float* Os[3];
    Os[0] = g_qp; Os[1] = g_kp; Os[2] = g_vp;
    for (int m = 0; m < 3; m++){
        __syncthreads();
        const float* W = Ws[m];
        for (int i = t; i < 64*64; i += 256){
            int o = i>>6, k = i&63;
            Wt[k*68+o] = W[i];
        }
        __syncthreads();
        float acc[4][4];
        #pragma unroll
        for (int i=0;i<4;i++) { acc[i][0]=0.f; acc[i][1]=0.f; acc[i][2]=0.f; acc[i][3]=0.f; }
        #pragma unroll 8
        for (int kk = 0; kk < 64; kk++){
            float4 a = *(const float4*)&Pt[kk*68 + tp*4];
            float4 w = *(const float4*)&Wt[kk*68 + to*4];
            float av[4] = {a.x,a.y,a.z,a.w};
            float wv[4] = {w.x,w.y,w.z,w.w};
            #pragma unroll
            for (int i=0;i<4;i++)
                #pragma unroll
                for (int j=0;j<4;j++) acc[i][j] += av[i]*wv[j];
        }
        float* O = Os[m];
        #pragma unroll
        for (int i = 0; i < 4; i++){
            float4 v4 = make_float4(acc[i][0], acc[i][1], acc[i][2], acc[i][3]);
            *(float4*)&O[(size_t)(r0 + tp*4 + i)*CC + to*4] = v4;
        }
    }
}

// ---------------- K3: fused KNN (distance GEMM + filtered top-40) -----------
// smem layout (floats):
//   Qs 64*132 | Cs 64*132 | pdS 128*132 | aq 128 | ac 128 |
//   ld 40*128 | li 40*128 | thr 128 | bufv 128*49 | bufi 128*49 | cnt 128
#define KNN_SMEM ((64*132*2 + 128*132 + 128 + 128 + 40*128*2 + 128 + 128*BPITCH*2 + 128)*4)
__global__ void __launch_bounds__(256,1) k_knn(){
    extern __shared__ float s[];
    float* Qs   = s;                      // [k][q], pitch 132
    float* Cs   = Qs  + 64*132;           // [k][c], pitch 132
    float* pdS  = Cs  + 64*132;           // [q][c], pitch 132 (fallback only)
    float* aq   = pdS + 128*132;          // 128
    float* ac   = aq  + 128;              // 128
    float* ld   = ac  + 128;              // top-40 values, [j*128+q]
    int*   li   = (int*)(ld + 40*128);    // top-40 indices
    float* thr  = (float*)(li + 40*128);  // 128 current 40th-best
    float* bufv = thr + 128;              // [q*BPITCH + slot]
    int*   bufi = (int*)(bufv + 128*BPITCH);
    int*   cnt  = bufi + 128*BPITCH;      // 128

    const int b  = blockIdx.y;
    const int q0 = blockIdx.x*128;
    const int t  = threadIdx.x;
    const float* pb = g_pcd + (size_t)b*NN*CC;
    const float* ab = g_aa + (size_t)b*NN;

    for (int i = t; i < 128*64; i += 256){
        int q = i>>6, k = i&63;
        Qs[k*132+q] = pb[(size_t)(q0+q)*CC + k];
    }
    if (t < 128){ aq[t] = ab[q0+t]; thr[t] = -3.4e38f; cnt[t] = 0; }
    for (int i = t; i < 40*128; i += 256){ ld[i] = -3.4e38f; li[i] = 0; }

    // per-query selection state lives in the owner thread's registers
    float vmin = -3.4e38f;
    int   minpos = 0;

    const int tq = t & 15, tc = t >> 4;

    for (int ct = 0; ct < NN/128; ct++){
        __syncthreads();
        const int c0 = ct*128;
        for (int i = t; i < 128*64; i += 256){
            int c = i>>6, k = i&63;
            Cs[k*132+c] = pb[(size_t)(c0+c)*CC + k];
        }
        if (t < 128) ac[t] = ab[c0+t];
        __syncthreads();

        // ---- 8x8 register-tile distance GEMM ----
        float acc[8][8];
        #pragma unroll
        for (int i=0;i<8;i++)
            #pragma unroll
            for (int j=0;j<8;j++) acc[i][j] = 0.f;
        #pragma unroll 4
        for (int kk = 0; kk < 64; kk++){
            float4 a0 = *(const float4*)&Qs[kk*132 + tq*8];
            float4 a1 = *(const float4*)&Qs[kk*132 + tq*8 + 4];
            float4 b0 = *(const float4*)&Cs[kk*132 + tc*8];
            float4 b1 = *(const float4*)&Cs[kk*132 + tc*8 + 4];
            float av[8] = {a0.x,a0.y,a0.z,a0.w,a1.x,a1.y,a1.z,a1.w};
            float bv[8] = {b0.x,b0.y,b0.z,b0.w,b1.x,b1.y,b1.z,b1.w};
            #pragma unroll
            for (int i=0;i<8;i++)
                #pragma unroll
                for (int j=0;j<8;j++) acc[i][j] += av[i]*bv[j];
        }

        // ---- finalize pd, write fallback tile, filter against threshold ----
        float acv[8];
        #pragma unroll
        for (int j=0;j<8;j++) acv[j] = ac[tc*8+j];
        #pragma unroll
        for (int i = 0; i < 8; i++){
            const int row = tq*8 + i;
            const float a_q = aq[row];
            float vr[8];
            #pragma unroll
            for (int j=0;j<8;j++) vr[j] = 2.f*acc[i][j] - a_q - acv[j];
            *(float4*)&pdS[row*132 + tc*8]     = make_float4(vr[0],vr[1],vr[2],vr[3]);
            *(float4*)&pdS[row*132 + tc*8 + 4] = make_float4(vr[4],vr[5],vr[6],vr[7]);
            const float th = thr[row];
            #pragma unroll
            for (int j=0;j<8;j++){
                if (vr[j] > th){
                    int pos = atomicAdd(&cnt[row], 1);
                    if (pos < BCAP){
                        bufv[row*BPITCH + pos] = vr[j];
                        bufi[row*BPITCH + pos] = c0 + tc*8 + j;
                    }
                }
            }
        }
        __syncthreads();

        // ---- per-query insertion (only survivors; fallback on overflow) ----
        if (t < 128){
            const int n = cnt[t];
            if (n > BCAP){
                // full serial scan of this query's pd row (tile 0 + rare overflow)
                for (int ci = 0; ci < 128; ci++){
                    float v = pdS[t*132 + ci];
                    if (v > vmin){
                        ld[minpos*128 + t] = v;
                        li[minpos*128 + t] = c0 + ci;
                        vmin = 3.4e38f;
                        #pragma unroll
                        for (int j = 0; j < KNB; j++){
                            float lv = ld[j*128 + t];
                            if (lv < vmin){ vmin = lv; minpos = j; }
                        }
                    }
                }
            } else {
                for (int s2 = 0; s2 < n; s2++){
                    float v = bufv[t*BPITCH + s2];
                    if (v > vmin){
                        ld[minpos*128 + t] = v;
                        li[minpos*128 + t] = bufi[t*BPITCH + s2];
                        vmin = 3.4e38f;
                        #pragma unroll
                        for (int j = 0; j < KNB; j++){
                            float lv = ld[j*128 + t];
                            if (lv < vmin){ vmin = lv; minpos = j; }
                        }
                    }
                }
            }
            cnt[t] = 0;
            thr[t] = vmin;
        }
    }
    __syncthreads();
    if (t < 128){
        int* dst = g_idx + ((size_t)b*NN + q0 + t)*KNB;
        #pragma unroll
        for (int j = 0; j < KNB; j++) dst[j] = li[j*128 + t];
    }
}

// ---------------- K4: attention via gathered projections (warp / point) -----
__global__ void __launch_bounds__(256) k_attn(const float* __restrict__ x){
    __shared__ float es[8][160];   // [warp][head*40+j]
    __shared__ int   sidx[8][40];
    const int w    = threadIdx.x >> 5;
    const int lane = threadIdx.x & 31;
    const int pg   = blockIdx.x*8 + w;       // global point id
    const int b    = pg >> 13, p = pg & (NN-1);
    const int* ip  = g_idx + (size_t)pg*KNB;
    sidx[w][lane] = ip[lane];
    if (lane < 8) sidx[w][lane+32] = ip[lane+32];
    const float* qrow = g_qp + (size_t)pg*CC;
    const float* kb   = g_kp + (size_t)b*NN*CC;
    const float* vb   = g_vp + (size_t)b*NN*CC;
    const float q0 = qrow[lane]    * 0.25f;   // fold 1/sqrt(D)=1/4
    const float q1 = qrow[lane+32] * 0.25f;
    const float kn0 = kb[(size_t)p*CC + lane];
    const float kn1 = kb[(size_t)p*CC + lane + 32];
    __syncwarp();
    const int hq = lane >> 4;   // 0/1 -> heads (hq, 2+hq)
    for (int j = 0; j < KNB; j++){
        const float* kr = kb + (size_t)sidx[w][j]*CC;
        float p0 = q0*(kr[lane]    - kn0);
        float p1 = q1*(kr[lane+32] - kn1);
        #pragma unroll
        for (int o = 8; o; o >>= 1){
            p0 += __shfl_xor_sync(0xffffffffu, p0, o);
            p1 += __shfl_xor_sync(0xffffffffu, p1, o);
        }
        if ((lane & 15) == 0){
            es[w][hq*40 + j]     = p0;
            es[w][(2+hq)*40 + j] = p1;
        }
    }
    __syncwarp();
    if (lane < 4){
        float m = -3.4e38f;
        for (int j = 0; j < KNB; j++) m = fmaxf(m, es[w][lane*40+j]);
        float ssum = 0.f;
        for (int j = 0; j < KNB; j++){
            float e = __expf(es[w][lane*40+j] - m);
            es[w][lane*40+j] = e;
            ssum += e;
        }
        float inv = 1.f/ssum;
        for (int j = 0; j < KNB; j++) es[w][lane*40+j] *= inv;
    }
    __syncwarp();
    const float vn0 = vb[(size_t)p*CC + lane];
    const float vn1 = vb[(size_t)p*CC + lane + 32];
    float a0 = 0.f, a1 = 0.f;
    for (int j = 0; j < KNB; j++){
        const float* vr = vb + (size_t)sidx[w][j]*CC;
        a0 += es[w][hq*40+j]     * (vr[lane]    - vn0);
        a1 += es[w][(2+hq)*40+j] * (vr[lane+32] - vn1);
    }
    const float* xb = x + (size_t)b*CC*NN;
    g_y1[(size_t)pg*CC + lane]      = a0 + xb[(size_t)lane*NN + p];
    g_y1[(size_t)pg*CC + lane + 32] = a1 + xb[(size_t)(lane+32)*NN + p];
}

// ---------------- K5: BN stats (deterministic two-stage) ---------------------
// 64 blocks x 512 rows each covers NPTS=32768 rows exactly.
__global__ void __launch_bounds__(256) k_stats(int srcsel, int which){
    __shared__ float ssum[256], ssq[256];
    const float* src = srcsel ? g_y2 : g_y1;
    const int t = threadIdx.x;
    const int c = t & 63, rl = t >> 6;
    const int r0 = blockIdx.x*512;
    float s = 0.f, s2 = 0.f;
    for (int r = rl; r < 512; r += 4){
        float v = src[(size_t)(r0+r)*CC + c];
        s += v; s2 += v*v;
    }
    ssum[t] = s; ssq[t] = s2;
    __syncthreads();
    if (t < 64){
        float a = ssum[t]+ssum[t+64]+ssum[t+128]+ssum[t+192];
        float q = ssq [t]+ssq [t+64]+ssq [t+128]+ssq [t+192];
        float* part = g_part + which*8192;
        part[blockIdx.x*128 + t]      = a;
        part[blockIdx.x*128 + 64 + t] = q;
    }
}

__global__ void k_bnfin(int which, const float* __restrict__ gamma,
                        const float* __restrict__ beta){
    const int c = threadIdx.x;   // 64 threads
    const float* part = g_part + which*8192;
    float s = 0.f, s2 = 0.f;
    for (int blk = 0; blk < 64; blk++){
        s  += part[blk*128 + c];
        s2 += part[blk*128 + 64 + c];
    }
    const float inv = 1.f/(float)NPTS;
    float m = s*inv;
    float v = s2*inv - m*m;
    float sc = gamma[c]*rsqrtf(v + 1e-5f);
    g_scb[which*128 + c]      = sc;
    g_scb[which*128 + 64 + c] = beta[c] - m*sc;
}

// ---------------- K6: fused FFN (BN1-apply + W1/lrelu + W2 + residual) ------
#define FFN_SMEM ((64*68 + 64*260 + 256*68 + 256*68)*4)
__global__ void __launch_bounds__(256,1) k_ffn(const float* __restrict__ W1,
                                               const float* __restrict__ W2){
    extern __shared__ float s[];
    float* Xs  = s;               // [c][r]  pitch 68   (x1, post-BN1)
    float* W1t = Xs  + 64*68;     // [c][o]  pitch 260
    float* Hs  = W1t + 64*260;    // [o][r]  pitch 68
    float* W2t = Hs  + 256*68;    // [o][c]  pitch 68
    __shared__ float sc1[64], bs1[64];
    const int t  = threadIdx.x;
    const int r0 = blockIdx.x*64;
    if (t < 64){ sc1[t] = g_scb[t]; bs1[t] = g_scb[64+t]; }
    for (int i = t; i < 256*64; i += 256){           // W1 (o,c) -> W1t[c][o]
        int o = i>>6, c = i&63;
        W1t[c*260 + o] = W1[i];
    }
    for (int i = t; i < 64*256; i += 256){           // W2 (c,o) -> W2t[o][c]
        int c = i>>8, o = i&255;
        W2t[o*68 + c] = W2[i];
    }
    __syncthreads();
    for (int i = t; i < 64*64; i += 256){            // x1 = BN1(y1)
        int r = i>>6, c = i&63;
        Xs[c*68 + r] = g_y1[(size_t)(r0+r)*CC + c]*sc1[c] + bs1[c];
    }
    __syncthreads();
    {   // stage 1: H[o][r] = lrelu( sum_c W1[o][c] * x1[c][r] )
        const int to = t >> 3, tr = t & 7;           // o = to*8.., r = tr*8..
        float acc[8][8];
        #pragma unroll
        for (int i=0;i<8;i++)
            #pragma unroll
            for (int j=0;j<8;j++) acc[i][j] = 0.f;
        #pragma unroll 4
        for (int k = 0; k < 64; k++){
            float4 a0 = *(const float4*)&Xs[k*68 + tr*8];
            float4 a1 = *(const float4*)&Xs[k*68 + tr*8 + 4];
            float4 w0 = *(const float4*)&W1t[k*260 + to*8];
            float4 w1 = *(const float4*)&W1t[k*260 + to*8 + 4];
            float av[8] = {a0.x,a0.y,a0.z,a0.w,a1.x,a1.y,a1.z,a1.w};
            float wv[8] = {w0.x,w0.y,w0.z,w0.w,w1.x,w1.y,w1.z,w1.w};
            #pragma unroll
            for (int oi=0;oi<8;oi++)
                #pragma unroll
                for (int ri=0;ri<8;ri++) acc[oi][ri] += wv[oi]*av[ri];
        }
        #pragma unroll
        for (int oi=0;oi<8;oi++)
            #pragma unroll
            for (int ri=0;ri<8;ri++){
                float h = acc[oi][ri];
                Hs[(to*8+oi)*68 + tr*8+ri] = (h > 0.f) ? h : 0.2f*h;
            }
    }
    __syncthreads();
    {   // stage 2: y2[r][c] = x1[c][r] + sum_o W2[c][o]*H[o][r]
        const int tr2 = t & 15, tc2 = t >> 4;        // r = tr2*4.., c = tc2*4..
        float acc[4][4];
        #pragma unroll
        for (int i=0;i<4;i++){ acc[i][0]=0.f; acc[i][1]=0.f; acc[i][2]=0.f; acc[i][3]=0.f; }
        #pragma unroll 8
        for (int o = 0; o < 256; o++){
            float4 h4 = *(const float4*)&Hs[o*68 + tr2*4];
            float4 w4 = *(const float4*)&W2t[o*68 + tc2*4];
            float hv[4] = {h4.x,h4.y,h4.z,h4.w};
            float wv[4] = {w4.x,w4.y,w4.z,w4.w};
            #pragma unroll
            for (int i=0;i<4;i++)
                #pragma unroll
                for (int j=0;j<4;j++) acc[i][j] += hv[i]*wv[j];
        }
        #pragma unroll
        for (int i = 0; i < 4; i++){
            int r = tr2*4 + i;
            float4 outv;
            outv.x = acc[i][0] + Xs[(tc2*4+0)*68 + r];
            outv.y = acc[i][1] + Xs[(tc2*4+1)*68 + r];
            outv.z = acc[i][2] + Xs[(tc2*4+2)*68 + r];
            outv.w = acc[i][3] + Xs[(tc2*4+3)*68 + r];
            *(float4*)&g_y2[(size_t)(r0+r)*CC + tc2*4] = outv;
        }
    }
}

// ---------------- K8: apply BN2 + transpose to (B,C,N) ----------------------
__global__ void __launch_bounds__(256) k_apply(float* __restrict__ out){
    __shared__ float tile[64][65];
    __shared__ float sc[64], bs[64];
    const int t = threadIdx.x;
    if (t < 64){ sc[t] = g_scb[128 + t]; bs[t] = g_scb[128 + 64 + t]; }
    const int n0 = blockIdx.x*64, b = blockIdx.y;
    __syncthreads();
    for (int i = t; i < 64*64; i += 256){
        int r = i>>6, c = i&63;
        tile[c][r] = g_y2[((size_t)b*NN + n0 + r)*CC + c]*sc[c] + bs[c];
    }
    __syncthreads();
    for (int i = t; i < 64*64; i += 256){
        int c = i>>6, n = i&63;
        out[((size_t)b*CC + c)*NN + n0 + n] = tile[c][n];
    }
}

// ---------------- launch -----------------------------------------------------
extern "C" void kernel_launch(void* const* d_in, const int* in_sizes, int n_in,
                              void* d_out, int out_size){
    const float* x  = (const float*)d_in[0];
    const float* Wq = (const float*)d_in[1];
    const float* Wk = (const float*)d_in[2];
    const float* Wv = (const float*)d_in[3];
    const float* W1 = (const float*)d_in[4];
    const float* W2 = (const float*)d_in[5];
    const float* g1 = (const float*)d_in[6];
    const float* b1 = (const float*)d_in[7];
    const float* g2 = (const float*)d_in[8];
    const float* b2 = (const float*)d_in[9];
    float* out = (float*)d_out;
    (void)in_sizes; (void)n_in; (void)out_size;

    cudaFuncSetAttribute(k_knn, cudaFuncAttributeMaxDynamicSharedMemorySize, KNN_SMEM);
    cudaFuncSetAttribute(k_ffn, cudaFuncAttributeMaxDynamicSharedMemorySize, FFN_SMEM);

    k_transpose<<<dim3(NN/32, CC/32, BB), dim3(32, 8)>>>(x);
    k_aa<<<NPTS/8, 256>>>();
    k_proj<<<NPTS/64, 256>>>(Wq, Wk, Wv);
    k_knn<<<dim3(NN/128, BB), 256, KNN_SMEM>>>();
    k_attn<<<NPTS/8, 256>>>(x);
    k_stats<<<64, 256>>>(0, 0);
    k_bnfin<<<1, 64>>>(0, g1, b1);
    k_ffn<<<NPTS/64, 256, FFN_SMEM>>>(W1, W2);
    k_stats<<<64, 256>>>(1, 1);
    k_bnfin<<<1, 64>>>(1, g2, b2);
    k_apply<<<dim3(NN/64, BB), 256>>>(out);
}

// round 6
// speedup vs baseline: 2.9533x; 1.0883x over previous
#include <cuda_runtime.h>

#define BB 4
#define CC 64
#define NN 8192
#define KNB 40
#define FFD 256
#define NPTS (BB*NN)
#define BCAP 48
#define BPITCH 49
#define CTILE 256

// ---------------- scratch (device globals: no allocations allowed) ----------
__device__ float g_pcd[NPTS*CC];   // (B,N,C) transposed input
__device__ float g_aa [NPTS];      // squared norms
__device__ float g_qp [NPTS*CC];   // pcd @ Wq^T
__device__ float g_kp [NPTS*CC];   // pcd @ Wk^T
__device__ float g_vp [NPTS*CC];   // pcd @ Wv^T
__device__ int   g_idx[NPTS*KNB];  // knn indices
__device__ float g_y1 [NPTS*CC];   // (B,N,C) x + attn_out  (pre-BN1)
__device__ float g_y2 [NPTS*CC];   // (B,N,C) x1 + ff       (pre-BN2)
__device__ float g_part[2*64*128]; // BN partial sums
__device__ float g_scb [2*128];    // BN scale/bias

// ---------------- K1: transpose x (B,C,N) -> pcd (B,N,C) --------------------
__global__ void k_transpose(const float* __restrict__ x){
    __shared__ float t[32][33];
    const int n0 = blockIdx.x*32, c0 = blockIdx.y*32, b = blockIdx.z;
    const float* xb = x + (size_t)b*CC*NN;
    #pragma unroll
    for (int i = threadIdx.y; i < 32; i += 8)
        t[i][threadIdx.x] = xb[(size_t)(c0+i)*NN + n0 + threadIdx.x];
    __syncthreads();
    float* pb = g_pcd + (size_t)b*NN*CC;
    #pragma unroll
    for (int i = threadIdx.y; i < 32; i += 8)
        pb[(size_t)(n0+i)*CC + c0 + threadIdx.x] = t[threadIdx.x][i];
}

// ---------------- K1b: aa[p] = sum_c pcd[p][c]^2 (warp per point) -----------
__global__ void k_aa(){
    const int p    = blockIdx.x*8 + (threadIdx.x>>5);
    const int lane = threadIdx.x & 31;
    const float* r = g_pcd + (size_t)p*CC;
    float a = r[lane]*r[lane] + r[lane+32]*r[lane+32];
    #pragma unroll
    for (int o = 16; o; o >>= 1) a += __shfl_xor_sync(0xffffffffu, a, o);
    if (!lane) g_aa[p] = a;
}

// ---------------- K2: qp/kp/vp = pcd @ W^T (64-pt tiles) ---------------------
__global__ void __launch_bounds__(256) k_proj(const float* __restrict__ Wq,
                                              const float* __restrict__ Wk,
                                              const float* __restrict__ Wv){
    __shared__ float Pt[64*68];   // [k][p]
    __shared__ float Wt[64*68];   // [k][o]
    const int t  = threadIdx.x;
    const int r0 = blockIdx.x*64;
    for (int i = t; i < 64*64; i += 256){
        int p = i>>6, k = i&63;
        Pt[k*68+p] = g_pcd[(size_t)(r0+p)*CC + k];
    }
    const int tp = t & 15, to = t >> 4;
    const float* Ws[3] = {Wq, Wk, Wv};
    float* Os[3];
    Os[0] = g_qp; Os[1] = g_kp; Os[2] = g_vp;
    for (int m = 0; m < 3; m++){
        __syncthreads();
        const float* W = Ws[m];
        for (int i = t; i < 64*64; i += 256){
            int o = i>>6, k = i&63;
            Wt[k*68+o] = W[i];
        }
        __syncthreads();
        float acc[4][4];
        #pragma unroll
        for (int i=0;i<4;i++) { acc[i][0]=0.f; acc[i][1]=0.f; acc[i][2]=0.f; acc[i][3]=0.f; }
        #pragma unroll 8
        for (int kk = 0; kk < 64; kk++){
            float4 a = *(const float4*)&Pt[kk*68 + tp*4];
            float4 w = *(const float4*)&Wt[kk*68 + to*4];
            float av[4] = {a.x,a.y,a.z,a.w};
            float wv[4] = {w.x,w.y,w.z,w.w};
            #pragma unroll
            for (int i=0;i<4;i++)
                #pragma unroll
                for (int j=0;j<4;j++) acc[i][j] += av[i]*wv[j];
        }
        float* O = Os[m];
        #pragma unroll
        for (int i = 0; i < 4; i++){
            float4 v4 = make_float4(acc[i][0], acc[i][1], acc[i][2], acc[i][3]);
            *(float4*)&O[(size_t)(r0 + tp*4 + i)*CC + to*4] = v4;
        }
    }
}

// ---------------- K3: fused KNN (distance GEMM + filtered top-40) -----------
// smem (floats): Qs 64*132 | Cs 64*260 | aq 128 | ac 256 |
//                ld 40*128 | li 40*128 | thr 128 | bufv 128*49 | bufi 128*49 |
//                cnt 128 | redo 8
#define KNN_SMEM ((64*132 + 64*260 + 128 + 256 + 40*128*2 + 128 + 128*BPITCH*2 + 128 + 8)*4)
__global__ void __launch_bounds__(256,1) k_knn(){
    extern __shared__ float s[];
    float* Qs   = s;                       // [k][q], pitch 132
    float* Cs   = Qs + 64*132;             // [k][c], pitch 260
    float* aq   = Cs + 64*260;             // 128
    float* ac   = aq + 128;                // 256
    float* ld   = ac + 256;                // top-40 values, [slot*128+q]
    int*   li   = (int*)(ld + 40*128);     // top-40 indices
    float* thr  = (float*)(li + 40*128);   // 128
    float* bufv = thr + 128;               // [q*BPITCH+slot]
    int*   bufi = (int*)(bufv + 128*BPITCH);
    int*   cnt  = bufi + 128*BPITCH;       // 128
    int*   s_redo = cnt + 128;             // 1 (+pad)

    const int b  = blockIdx.y;
    const int q0 = blockIdx.x*128;
    const int t  = threadIdx.x;
    const int tq = t >> 4;                 // rows tq*8 .. +8
    const int tc = t & 15;                 // cols tc*4 + 64*chunk
    const float* pb = g_pcd + (size_t)b*NN*CC;
    const float* ab = g_aa + (size_t)b*NN;

    for (int i = t; i < 128*64; i += 256){
        int q = i>>6, k = i&63;
        Qs[k*132+q] = pb[(size_t)(q0+q)*CC + k];
    }
    if (t < 128){ aq[t] = ab[q0+t]; thr[t] = -3.4e38f; cnt[t] = 0; }
    if (t == 0) s_redo[0] = 0;

    float vmin = -3.4e38f;   // owner-thread (t<128) selection state
    int   minpos = 0;

    for (int ct = 0; ct < NN/CTILE; ct++){
        __syncthreads();
        const int c0 = ct*CTILE;
        for (int i = t; i < CTILE*64; i += 256){
            int c = i>>6, k = i&63;
            Cs[k*260+c] = pb[(size_t)(c0+c)*CC + k];
        }
        ac[t] = ab[c0+t];
        __syncthreads();

        // ---- 8x16 register-tile distance GEMM ----
        float acc[8][16];
        #pragma unroll
        for (int i=0;i<8;i++)
            #pragma unroll
            for (int j=0;j<16;j++) acc[i][j] = 0.f;
        #pragma unroll 2
        for (int kk = 0; kk < 64; kk++){
            float4 qa0 = *(const float4*)&Qs[kk*132 + tq*8];
            float4 qa1 = *(const float4*)&Qs[kk*132 + tq*8 + 4];
            float4 cb0 = *(const float4*)&Cs[kk*260 + tc*4];
            float4 cb1 = *(const float4*)&Cs[kk*260 + tc*4 + 64];
            float4 cb2 = *(const float4*)&Cs[kk*260 + tc*4 + 128];
            float4 cb3 = *(const float4*)&Cs[kk*260 + tc*4 + 192];
            float qa[8] = {qa0.x,qa0.y,qa0.z,qa0.w,qa1.x,qa1.y,qa1.z,qa1.w};
            float cb[16] = {cb0.x,cb0.y,cb0.z,cb0.w, cb1.x,cb1.y,cb1.z,cb1.w,
                            cb2.x,cb2.y,cb2.z,cb2.w, cb3.x,cb3.y,cb3.z,cb3.w};
            #pragma unroll
            for (int i=0;i<8;i++)
                #pragma unroll
                for (int j=0;j<16;j++) acc[i][j] += qa[i]*cb[j];
        }

        // ---- finalize pd in registers ----
        float acv[16];
        #pragma unroll
        for (int ch=0; ch<4; ch++){
            float4 a4 = *(const float4*)&ac[ch*64 + tc*4];
            acv[ch*4+0]=a4.x; acv[ch*4+1]=a4.y; acv[ch*4+2]=a4.z; acv[ch*4+3]=a4.w;
        }
        unsigned pend[8];
        #pragma unroll
        for (int i=0;i<8;i++){
            const float a_q = aq[tq*8+i];
            #pragma unroll
            for (int j=0;j<16;j++) acc[i][j] = 2.f*acc[i][j] - a_q - acv[j];
            pend[i] = 0xFFFFu;
        }

        if (ct == 0){
            // direct-init: first 40 candidates fill slots 0..39 (one writer each)
            #pragma unroll
            for (int j=0;j<16;j++){
                int cg = (j>>2)*64 + tc*4 + (j&3);
                if (cg < KNB){
                    #pragma unroll
                    for (int i=0;i<8;i++){
                        ld[cg*128 + tq*8+i] = acc[i][j];
                        li[cg*128 + tq*8+i] = cg;
                    }
                    #pragma unroll
                    for (int i=0;i<8;i++) pend[i] &= ~(1u<<j);
                }
            }
            __syncthreads();
            if (t < 128){
                vmin = 3.4e38f;
                #pragma unroll
                for (int j=0;j<KNB;j++){
                    float lv = ld[j*128+t];
                    if (lv < vmin){ vmin = lv; minpos = j; }
                }
                thr[t] = vmin;
            }
        }

        // ---- filter / insert retry loop (handles any overflow exactly) ----
        for (;;){
            if (t == 0) s_redo[0] = 0;
            __syncthreads();                       // reset + thr visible
            #pragma unroll
            for (int i=0;i<8;i++){
                unsigned p = pend[i];
                if (!p) continue;
                const int row = tq*8+i;
                const float th = thr[row];
                #pragma unroll
                for (int j=0;j<16;j++){
                    if (!(p & (1u<<j))) continue;
                    float v = acc[i][j];
                    if (v <= th){ p &= ~(1u<<j); continue; }
                    int pos = atomicAdd(&cnt[row], 1);
                    if (pos < BCAP){
                        bufv[row*BPITCH+pos] = v;
                        bufi[row*BPITCH+pos] = c0 + (j>>2)*64 + tc*4 + (j&3);
                        p &= ~(1u<<j);
                    } else s_redo[0] = 1;
                }
                pend[i] = p;
            }
            __syncthreads();
            if (t < 128){
                int n = cnt[t]; if (n > BCAP) n = BCAP;
                for (int s2 = 0; s2 < n; s2++){
                    float v = bufv[t*BPITCH+s2];
                    if (v > vmin){
                        ld[minpos*128+t] = v;
                        li[minpos*128+t] = bufi[t*BPITCH+s2];
                        vmin = 3.4e38f;
                        #pragma unroll
                        for (int j=0;j<KNB;j++){
                            float lv = ld[j*128+t];
                            if (lv < vmin){ vmin = lv; minpos = j; }
                        }
                    }
                }
                cnt[t] = 0;
                thr[t] = vmin;
            }
            int r = s_redo[0];          // written only in pre-sync filter epoch
            __syncthreads();
            if (!r) break;
        }
    }
    __syncthreads();
    if (t < 128){
        int* dst = g_idx + ((size_t)b*NN + q0 + t)*KNB;
        #pragma unroll
        for (int j = 0; j < KNB; j++) dst[j] = li[j*128 + t];
    }
}

// ---------------- K4: attention via gathered projections (warp / point) -----
__global__ void __launch_bounds__(256) k_attn(const float* __restrict__ x){
    __shared__ float es[8][160];   // [warp][head*40+j]
    __shared__ int   sidx[8][40];
    const int w    = threadIdx.x >> 5;
    const int lane = threadIdx.x & 31;
    const int pg   = blockIdx.x*8 + w;       // global point id
    const int b    = pg >> 13, p = pg & (NN-1);
    const int* ip  = g_idx + (size_t)pg*KNB;
    sidx[w][lane] = ip[lane];
    if (lane < 8) sidx[w][lane+32] = ip[lane+32];
    const float* qrow = g_qp + (size_t)pg*CC;
    const float* kb   = g_kp + (size_t)b*NN*CC;
    const float* vb   = g_vp + (size_t)b*NN*CC;
    const float q0 = qrow[lane]    * 0.25f;   // fold 1/sqrt(D)=1/4
    const float q1 = qrow[lane+32] * 0.25f;
    const float kn0 = kb[(size_t)p*CC + lane];
    const float kn1 = kb[(size_t)p*CC + lane + 32];
    __syncwarp();
    const int hq = lane >> 4;   // 0/1 -> heads (hq, 2+hq)
    for (int j = 0; j < KNB; j++){
        const float* kr = kb + (size_t)sidx[w][j]*CC;
        float p0 = q0*(kr[lane]    - kn0);
        float p1 = q1*(kr[lane+32] - kn1);
        #pragma unroll
        for (int o = 8; o; o >>= 1){
            p0 += __shfl_xor_sync(0xffffffffu, p0, o);
            p1 += __shfl_xor_sync(0xffffffffu, p1, o);
        }
        if ((lane & 15) == 0){
            es[w][hq*40 + j]     = p0;
            es[w][(2+hq)*40 + j] = p1;
        }
    }
    __syncwarp();
    if (lane < 4){
        float m = -3.4e38f;
        for (int j = 0; j < KNB; j++) m = fmaxf(m, es[w][lane*40+j]);
        float ssum = 0.f;
        for (int j = 0; j < KNB; j++){
            float e = __expf(es[w][lane*40+j] - m);
            es[w][lane*40+j] = e;
            ssum += e;
        }
        float inv = 1.f/ssum;
        for (int j = 0; j < KNB; j++) es[w][lane*40+j] *= inv;
    }
    __syncwarp();
    const float vn0 = vb[(size_t)p*CC + lane];
    const float vn1 = vb[(size_t)p*CC + lane + 32];
    float a0 = 0.f, a1 = 0.f;
    for (int j = 0; j < KNB; j++){
        const float* vr = vb + (size_t)sidx[w][j]*CC;
        a0 += es[w][hq*40+j]     * (vr[lane]    - vn0);
        a1 += es[w][(2+hq)*40+j] * (vr[lane+32] - vn1);
    }
    const float* xb = x + (size_t)b*CC*NN;
    g_y1[(size_t)pg*CC + lane]      = a0 + xb[(size_t)lane*NN + p];
    g_y1[(size_t)pg*CC + lane + 32] = a1 + xb[(size_t)(lane+32)*NN + p];
}

// ---------------- K5: BN stats (deterministic two-stage) ---------------------
// 64 blocks x 512 rows each covers NPTS=32768 rows exactly.
__global__ void __launch_bounds__(256) k_stats(int srcsel, int which){
    __shared__ float ssum[256], ssq[256];
    const float* src = srcsel ? g_y2 : g_y1;
    const int t = threadIdx.x;
    const int c = t & 63, rl = t >> 6;
    const int r0 = blockIdx.x*512;
    float s = 0.f, s2 = 0.f;
    for (int r = rl; r < 512; r += 4){
        float v = src[(size_t)(r0+r)*CC + c];
        s += v; s2 += v*v;
    }
    ssum[t] = s; ssq[t] = s2;
    __syncthreads();
    if (t < 64){
        float a = ssum[t]+ssum[t+64]+ssum[t+128]+ssum[t+192];
        float q = ssq [t]+ssq [t+64]+ssq [t+128]+ssq [t+192];
        float* part = g_part + which*8192;
        part[blockIdx.x*128 + t]      = a;
        part[blockIdx.x*128 + 64 + t] = q;
    }
}

__global__ void k_bnfin(int which, const float* __restrict__ gamma,
                        const float* __restrict__ beta){
    const int c = threadIdx.x;   // 64 threads
    const float* part = g_part + which*8192;
    float s = 0.f, s2 = 0.f;
    for (int blk = 0; blk < 64; blk++){
        s  += part[blk*128 + c];
        s2 += part[blk*128 + 64 + c];
    }
    const float inv = 1.f/(float)NPTS;
    float m = s*inv;
    float v = s2*inv - m*m;
    float sc = gamma[c]*rsqrtf(v + 1e-5f);
    g_scb[which*128 + c]      = sc;
    g_scb[which*128 + 64 + c] = beta[c] - m*sc;
}

// ---------------- K6: fused FFN (BN1-apply + W1/lrelu + W2 + residual) ------
#define FFN_SMEM ((64*68 + 64*260 + 256*68 + 256*68)*4)
__global__ void __launch_bounds__(256,1) k_ffn(const float* __restrict__ W1,
                                               const float* __restrict__ W2){
    extern __shared__ float s[];
    float* Xs  = s;               // [c][r]  pitch 68   (x1, post-BN1)
    float* W1t = Xs  + 64*68;     // [c][o]  pitch 260
    float* Hs  = W1t + 64*260;    // [o][r]  pitch 68
    float* W2t = Hs  + 256*68;    // [o][c]  pitch 68
    __shared__ float sc1[64], bs1[64];
    const int t  = threadIdx.x;
    const int r0 = blockIdx.x*64;
    if (t < 64){ sc1[t] = g_scb[t]; bs1[t] = g_scb[64+t]; }
    for (int i = t; i < 256*64; i += 256){           // W1 (o,c) -> W1t[c][o]
        int o = i>>6, c = i&63;
        W1t[c*260 + o] = W1[i];
    }
    for (int i = t; i < 64*256; i += 256){           // W2 (c,o) -> W2t[o][c]
        int c = i>>8, o = i&255;
        W2t[o*68 + c] = W2[i];
    }
    __syncthreads();
    for (int i = t; i < 64*64; i += 256){            // x1 = BN1(y1)
        int r = i>>6, c = i&63;
        Xs[c*68 + r] = g_y1[(size_t)(r0+r)*CC + c]*sc1[c] + bs1[c];
    }
    __syncthreads();
    {   // stage 1: H[o][r] = lrelu( sum_c W1[o][c] * x1[c][r] )
        const int to = t >> 3, tr = t & 7;           // o = to*8.., r = tr*8..
        float acc[8][8];
        #pragma unroll
        for (int i=0;i<8;i++)
            #pragma unroll
            for (int j=0;j<8;j++) acc[i][j] = 0.f;
        #pragma unroll 4
        for (int k = 0; k < 64; k++){
            float4 a0 = *(const float4*)&Xs[k*68 + tr*8];
            float4 a1 = *(const float4*)&Xs[k*68 + tr*8 + 4];
            float4 w0 = *(const float4*)&W1t[k*260 + to*8];
            float4 w1 = *(const float4*)&W1t[k*260 + to*8 + 4];
            float av[8] = {a0.x,a0.y,a0.z,a0.w,a1.x,a1.y,a1.z,a1.w};
            float wv[8] = {w0.x,w0.y,w0.z,w0.w,w1.x,w1.y,w1.z,w1.w};
            #pragma unroll
            for (int oi=0;oi<8;oi++)
                #pragma unroll
                for (int ri=0;ri<8;ri++) acc[oi][ri] += wv[oi]*av[ri];
        }
        #pragma unroll
        for (int oi=0;oi<8;oi++)
            #pragma unroll
            for (int ri=0;ri<8;ri++){
                float h = acc[oi][ri];
                Hs[(to*8+oi)*68 + tr*8+ri] = (h > 0.f) ? h : 0.2f*h;
            }
    }
    __syncthreads();
    {   // stage 2: y2[r][c] = x1[c][r] + sum_o W2[c][o]*H[o][r]
        const int tr2 = t & 15, tc2 = t >> 4;        // r = tr2*4.., c = tc2*4..
        float acc[4][4];
        #pragma unroll
        for (int i=0;i<4;i++){ acc[i][0]=0.f; acc[i][1]=0.f; acc[i][2]=0.f; acc[i][3]=0.f; }
        #pragma unroll 8
        for (int o = 0; o < 256; o++){
            float4 h4 = *(const float4*)&Hs[o*68 + tr2*4];
            float4 w4 = *(const float4*)&W2t[o*68 + tc2*4];
            float hv[4] = {h4.x,h4.y,h4.z,h4.w};
            float wv[4] = {w4.x,w4.y,w4.z,w4.w};
            #pragma unroll
            for (int i=0;i<4;i++)
                #pragma unroll
                for (int j=0;j<4;j++) acc[i][j] += hv[i]*wv[j];
        }
        #pragma unroll
        for (int i = 0; i < 4; i++){
            int r = tr2*4 + i;
            float4 outv;
            outv.x = acc[i][0] + Xs[(tc2*4+0)*68 + r];
            outv.y = acc[i][1] + Xs[(tc2*4+1)*68 + r];
            outv.z = acc[i][2] + Xs[(tc2*4+2)*68 + r];
            outv.w = acc[i][3] + Xs[(tc2*4+3)*68 + r];
            *(float4*)&g_y2[(size_t)(r0+r)*CC + tc2*4] = outv;
        }
    }
}

// ---------------- K8: apply BN2 + transpose to (B,C,N) ----------------------
__global__ void __launch_bounds__(256) k_apply(float* __restrict__ out){
    __shared__ float tile[64][65];
    __shared__ float sc[64], bs[64];
    const int t = threadIdx.x;
    if (t < 64){ sc[t] = g_scb[128 + t]; bs[t] = g_scb[128 + 64 + t]; }
    const int n0 = blockIdx.x*64, b = blockIdx.y;
    __syncthreads();
    for (int i = t; i < 64*64; i += 256){
        int r = i>>6, c = i&63;
        tile[c][r] = g_y2[((size_t)b*NN + n0 + r)*CC + c]*sc[c] + bs[c];
    }
    __syncthreads();
    for (int i = t; i < 64*64; i += 256){
        int c = i>>6, n = i&63;
        out[((size_t)b*CC + c)*NN + n0 + n] = tile[c][n];
    }
}

// ---------------- launch -----------------------------------------------------
extern "C" void kernel_launch(void* const* d_in, const int* in_sizes, int n_in,
                              void* d_out, int out_size){
    const float* x  = (const float*)d_in[0];
    const float* Wq = (const float*)d_in[1];
    const float* Wk = (const float*)d_in[2];
    const float* Wv = (const float*)d_in[3];
    const float* W1 = (const float*)d_in[4];
    const float* W2 = (const float*)d_in[5];
    const float* g1 = (const float*)d_in[6];
    const float* b1 = (const float*)d_in[7];
    const float* g2 = (const float*)d_in[8];
    const float* b2 = (const float*)d_in[9];
    float* out = (float*)d_out;
    (void)in_sizes; (void)n_in; (void)out_size;

    cudaFuncSetAttribute(k_knn, cudaFuncAttributeMaxDynamicSharedMemorySize, KNN_SMEM);
    cudaFuncSetAttribute(k_ffn, cudaFuncAttributeMaxDynamicSharedMemorySize, FFN_SMEM);

    k_transpose<<<dim3(NN/32, CC/32, BB), dim3(32, 8)>>>(x);
    k_aa<<<NPTS/8, 256>>>();
    k_proj<<<NPTS/64, 256>>>(Wq, Wk, Wv);
    k_knn<<<dim3(NN/128, BB), 256, KNN_SMEM>>>();
    k_attn<<<NPTS/8, 256>>>(x);
    k_stats<<<64, 256>>>(0, 0);
    k_bnfin<<<1, 64>>>(0, g1, b1);
    k_ffn<<<NPTS/64, 256, FFN_SMEM>>>(W1, W2);
    k_stats<<<64, 256>>>(1, 1);
    k_bnfin<<<1, 64>>>(1, g2, b2);
    k_apply<<<dim3(NN/64, BB), 256>>>(out);
}

// round 8
// speedup vs baseline: 3.8143x; 1.2915x over previous
#include <cuda_runtime.h>
#include <cuda_bf16.h>
#include <cstdint>

#define BB 4
#define CC 64
#define NN 8192
#define KNB 40
#define FFD 256
#define NPTS (BB*NN)
#define BCAP 48
#define BPITCH 49
#define CTILE 128

// ---------------- scratch (device globals: no allocations allowed) ----------
__device__ float g_pcd[NPTS*CC];   // (B,N,C) transposed input
__device__ __nv_bfloat16 g_pch[NPTS*CC]; // bf16 hi split
__device__ __nv_bfloat16 g_pcl[NPTS*CC]; // bf16 lo split
__device__ float g_aa [NPTS];      // squared norms
__device__ float g_qp [NPTS*CC];   // pcd @ Wq^T
__device__ float g_kp [NPTS*CC];   // pcd @ Wk^T
__device__ float g_vp [NPTS*CC];   // pcd @ Wv^T
__device__ int   g_idx[NPTS*KNB];  // knn indices
__device__ float g_y1 [NPTS*CC];
__device__ float g_y2 [NPTS*CC];
__device__ float g_part[2*64*128];
__device__ float g_scb [2*128];

// ---------------- K1: transpose x (B,C,N) -> pcd (B,N,C) --------------------
__global__ void k_transpose(const float* __restrict__ x){
    __shared__ float t[32][33];
    const int n0 = blockIdx.x*32, c0 = blockIdx.y*32, b = blockIdx.z;
    const float* xb = x + (size_t)b*CC*NN;
    #pragma unroll
    for (int i = threadIdx.y; i < 32; i += 8)
        t[i][threadIdx.x] = xb[(size_t)(c0+i)*NN + n0 + threadIdx.x];
    __syncthreads();
    float* pb = g_pcd + (size_t)b*NN*CC;
    #pragma unroll
    for (int i = threadIdx.y; i < 32; i += 8)
        pb[(size_t)(n0+i)*CC + c0 + threadIdx.x] = t[threadIdx.x][i];
}

// ---------------- K1b: aa + bf16 hi/lo split ---------------------------------
__global__ void k_aa(){
    const int p    = blockIdx.x*8 + (threadIdx.x>>5);
    const int lane = threadIdx.x & 31;
    const float* r = g_pcd + (size_t)p*CC;
    float a = r[lane]*r[lane] + r[lane+32]*r[lane+32];
    #pragma unroll
    for (int o = 16; o; o >>= 1) a += __shfl_xor_sync(0xffffffffu, a, o);
    if (!lane) g_aa[p] = a;
}
__global__ void k_split(){
    const int i = blockIdx.x*256 + threadIdx.x;
    float v = g_pcd[i];
    __nv_bfloat16 h = __float2bfloat16(v);
    g_pch[i] = h;
    g_pcl[i] = __float2bfloat16(v - __bfloat162float(h));
}

// ---------------- K2: qp/kp/vp = pcd @ W^T (64-pt tiles) ---------------------
__global__ void __launch_bounds__(256) k_proj(const float* __restrict__ Wq,
                                              const float* __restrict__ Wk,
                                              const float* __restrict__ Wv){
    __shared__ float Pt[64*68];   // [k][p]
    __shared__ float Wt[64*68];   // [k][o]
    const int t  = threadIdx.x;
    const int r0 = blockIdx.x*64;
    for (int i = t; i < 64*64; i += 256){
        int p = i>>6, k = i&63;
        Pt[k*68+p] = g_pcd[(size_t)(r0+p)*CC + k];
    }
    const int tp = t & 15, to = t >> 4;
    const float* Ws[3] = {Wq, Wk, Wv};
    float* Os[3];
    Os[0] = g_qp; Os[1] = g_kp; Os[2] = g_vp;
    for (int m = 0; m < 3; m++){
        __syncthreads();
        const float* W = Ws[m];
        for (int i = t; i < 64*64; i += 256){
            int o = i>>6, k = i&63;
            Wt[k*68+o] = W[i];
        }
        __syncthreads();
        float acc[4][4];
        #pragma unroll
        for (int i=0;i<4;i++) { acc[i][0]=0.f; acc[i][1]=0.f; acc[i][2]=0.f; acc[i][3]=0.f; }
        #pragma unroll 8
        for (int kk = 0; kk < 64; kk++){
            float4 a = *(const float4*)&Pt[kk*68 + tp*4];
            float4 w = *(const float4*)&Wt[kk*68 + to*4];
            float av[4] = {a.x,a.y,a.z,a.w};
            float wv[4] = {w.x,w.y,w.z,w.w};
            #pragma unroll
            for (int i=0;i<4;i++)
                #pragma unroll
                for (int j=0;j<4;j++) acc[i][j] += av[i]*wv[j];
        }
        float* O = Os[m];
        #pragma unroll
        for (int i = 0; i < 4; i++){
            float4 v4 = make_float4(acc[i][0], acc[i][1], acc[i][2], acc[i][3]);
            *(float4*)&O[(size_t)(r0 + tp*4 + i)*CC + to*4] = v4;
        }
    }
}

// ---------------- K3: KNN via mma.sync bf16-split GEMM + filtered top-40 ----
// smem bytes: QH@0 18432 | QL@18432 | CH@36864 | CL@55296 | float region @73728
#define PITCHB 144            // 72 bf16 per row
#define QH_OFF 0
#define QL_OFF 18432
#define CH_OFF 36864
#define CL_OFF 55296
#define FX_OFF 73728
#define KNN_SMEM (FX_OFF + 23432*4)

#define MMA_BF16(dd, a, b0_, b1_) \
    asm volatile("mma.sync.aligned.m16n8k16.row.col.f32.bf16.bf16.f32 " \
        "{%0,%1,%2,%3}, {%4,%5,%6,%7}, {%8,%9}, {%0,%1,%2,%3};" \
        : "+f"((dd)[0]), "+f"((dd)[1]), "+f"((dd)[2]), "+f"((dd)[3]) \
        : "r"((a)[0]), "r"((a)[1]), "r"((a)[2]), "r"((a)[3]), \
          "r"(b0_), "r"(b1_))

__global__ void __launch_bounds__(256,1) k_knn(){
    extern __shared__ char sm[];
    float* fx   = (float*)(sm + FX_OFF);
    float* aq   = fx;            // 128
    float* ac   = fx + 128;      // 256 (128 used)
    float* thr  = fx + 384;      // 128
    float* ld   = fx + 512;      // 40*128
    float* bufv = fx + 5632;     // 128*49
    int*   li   = (int*)(fx + 11904);  // 40*128
    int*   bufi = (int*)(fx + 17024);  // 128*49
    int*   cnt  = (int*)(fx + 23296);  // 128
    int*   s_redo = (int*)(fx + 23424);

    const int b  = blockIdx.y;
    const int q0 = blockIdx.x*128;
    const int t  = threadIdx.x;
    const int wid  = t >> 5;
    const int lane = t & 31;
    const int g  = lane >> 2;          // group row 0..7
    const int qq = lane & 3;           // quad col 0..3
    const int qb = (wid & 3)*32;       // warp's query base (row within tile)
    const int cb = (wid >> 2)*64;      // warp's candidate-col base

    // ---- stage Q tiles (bf16 hi/lo) ----
    {
        const uint4* qh = (const uint4*)(g_pch + (size_t)(b*NN + q0)*CC);
        const uint4* ql = (const uint4*)(g_pcl + (size_t)(b*NN + q0)*CC);
        for (int i = t; i < 128*8; i += 256){
            int row = i >> 3, c16 = i & 7;
            int off = row*PITCHB + c16*16;
            *(uint4*)(sm + QH_OFF + off) = qh[i];
            *(uint4*)(sm + QL_OFF + off) = ql[i];
        }
    }
    if (t < 128){ aq[t] = g_aa[(size_t)b*NN + q0 + t]; thr[t] = -3.4e38f; cnt[t] = 0; }

    float vmin = -3.4e38f;   // owner state (t<128 owns query t)
    int   minpos = 0;

    for (int ct = 0; ct < NN/CTILE; ct++){
        __syncthreads();   // previous tile fully consumed
        const int c0 = ct*CTILE;

        // ---- stage C tiles (bf16 hi/lo) + ac ----
        {
            const uint4* ch = (const uint4*)(g_pch + (size_t)(b*NN + c0)*CC);
            const uint4* cl = (const uint4*)(g_pcl + (size_t)(b*NN + c0)*CC);
            for (int i = t; i < 128*8; i += 256){
                int row = i >> 3, c16 = i & 7;
                int off = row*PITCHB + c16*16;
                *(uint4*)(sm + CH_OFF + off) = ch[i];
                *(uint4*)(sm + CL_OFF + off) = cl[i];
            }
            if (t < 128) ac[t] = g_aa[(size_t)b*NN + c0 + t];
        }
        __syncthreads();

        // ---- warp GEMM: 32q x 64c via m16n8k16, 3-term bf16 split ----
        float d[2][8][4];
        #pragma unroll
        for (int mi=0;mi<2;mi++)
            #pragma unroll
            for (int ni=0;ni<8;ni++)
                #pragma unroll
                for (int j=0;j<4;j++) d[mi][ni][j] = 0.f;

        #pragma unroll
        for (int kc = 0; kc < 4; kc++){
            const int koff = kc*32 + qq*4;   // bytes within row
            uint32_t ah[2][4], al[2][4];
            #pragma unroll
            for (int mi=0;mi<2;mi++){
                int r0b = (qb + mi*16 + g)*PITCHB + koff;
                int r1b = r0b + 8*PITCHB;
                ah[mi][0] = *(const uint32_t*)(sm + QH_OFF + r0b);
                ah[mi][1] = *(const uint32_t*)(sm + QH_OFF + r1b);
                ah[mi][2] = *(const uint32_t*)(sm + QH_OFF + r0b + 16);
                ah[mi][3] = *(const uint32_t*)(sm + QH_OFF + r1b + 16);
                al[mi][0] = *(const uint32_t*)(sm + QL_OFF + r0b);
                al[mi][1] = *(const uint32_t*)(sm + QL_OFF + r1b);
                al[mi][2] = *(const uint32_t*)(sm + QL_OFF + r0b + 16);
                al[mi][3] = *(const uint32_t*)(sm + QL_OFF + r1b + 16);
            }
            #pragma unroll
            for (int ni=0;ni<8;ni++){
                int crb = (cb + ni*8 + g)*PITCHB + koff;
                uint32_t bh0 = *(const uint32_t*)(sm + CH_OFF + crb);
                uint32_t bh1 = *(const uint32_t*)(sm + CH_OFF + crb + 16);
                uint32_t bl0 = *(const uint32_t*)(sm + CL_OFF + crb);
                uint32_t bl1 = *(const uint32_t*)(sm + CL_OFF + crb + 16);
                #pragma unroll
                for (int mi=0;mi<2;mi++){
                    MMA_BF16(d[mi][ni], ah[mi], bh0, bh1);
                    MMA_BF16(d[mi][ni], ah[mi], bl0, bl1);
                    MMA_BF16(d[mi][ni], al[mi], bh0, bh1);
                }
            }
        }

        // ---- fold pd = 2*dot - aq - ac into fragments ----
        #pragma unroll
        for (int mi=0;mi<2;mi++){
            float aq0 = aq[qb + mi*16 + g];
            float aq1 = aq[qb + mi*16 + g + 8];
            #pragma unroll
            for (int ni=0;ni<8;ni++){
                float ac0 = ac[cb + ni*8 + qq*2];
                float ac1 = ac[cb + ni*8 + qq*2 + 1];
                d[mi][ni][0] = 2.f*d[mi][ni][0] - aq0 - ac0;
                d[mi][ni][1] = 2.f*d[mi][ni][1] - aq0 - ac1;
                d[mi][ni][2] = 2.f*d[mi][ni][2] - aq1 - ac0;
                d[mi][ni][3] = 2.f*d[mi][ni][3] - aq1 - ac1;
            }
        }

        unsigned pend[2] = {0xFFFFFFFFu, 0xFFFFFFFFu};

        if (ct == 0){
            // direct-init: cols 0..39 (ni<5 in cb==0 warps) fill slots directly
            if (cb == 0){
                #pragma unroll
                for (int mi=0;mi<2;mi++){
                    #pragma unroll
                    for (int ni=0;ni<5;ni++){
                        #pragma unroll
                        for (int j=0;j<4;j++){
                            int col = ni*8 + qq*2 + (j&1);
                            int row = qb + mi*16 + g + ((j>>1)<<3);
                            ld[col*128 + row] = d[mi][ni][j];
                            li[col*128 + row] = col;
                        }
                    }
                    pend[mi] &= 0xFFF00000u;   // clear ni 0..4
                }
            }
            __syncthreads();
            if (t < 128){
                vmin = 3.4e38f;
                #pragma unroll
                for (int j = 0; j < KNB; j++){
                    float lv = ld[j*128 + t];
                    if (lv < vmin){ vmin = lv; minpos = j; }
                }
                thr[t] = vmin;
            }
        }

        // ---- filter / insert retry loop ----
        for (;;){
            if (t == 0) s_redo[0] = 0;
            __syncthreads();
            #pragma unroll
            for (int mi=0;mi<2;mi++){
                unsigned p = pend[mi];
                if (!p) continue;
                const int r0w = qb + mi*16 + g;
                const float th0 = thr[r0w], th1 = thr[r0w + 8];
                #pragma unroll
                for (int ni=0;ni<8;ni++){
                    #pragma unroll
                    for (int j=0;j<4;j++){
                        const unsigned bit = 1u << (ni*4 + j);
                        if (!(p & bit)) continue;
                        float v = d[mi][ni][j];
                        int row = r0w + ((j>>1)<<3);
                        float th = (j>>1) ? th1 : th0;
                        if (v <= th){ p &= ~bit; continue; }
                        int pos = atomicAdd(&cnt[row], 1);
                        if (pos < BCAP){
                            bufv[row*BPITCH + pos] = v;
                            bufi[row*BPITCH + pos] = c0 + cb + ni*8 + qq*2 + (j&1);
                            p &= ~bit;
                        } else s_redo[0] = 1;
                    }
                }
                pend[mi] = p;
            }
            __syncthreads();
            if (t < 128){
                int n = cnt[t]; if (n > BCAP) n = BCAP;
                for (int s2 = 0; s2 < n; s2++){
                    float v = bufv[t*BPITCH + s2];
                    if (v > vmin){
                        ld[minpos*128 + t] = v;
                        li[minpos*128 + t] = bufi[t*BPITCH + s2];
                        vmin = 3.4e38f;
                        #pragma unroll
                        for (int j = 0; j < KNB; j++){
                            float lv = ld[j*128 + t];
                            if (lv < vmin){ vmin = lv; minpos = j; }
                        }
                    }
                }
                cnt[t] = 0;
                thr[t] = vmin;
            }
            int r = s_redo[0];
            __syncthreads();
            if (!r) break;
        }
    }

    __syncthreads();
    if (t < 128){
        int* dst = g_idx + ((size_t)b*NN + q0 + t)*KNB;
        #pragma unroll
        for (int j = 0; j < KNB; j++) dst[j] = li[j*128 + t];
    }
}

// ---------------- K4: attention via gathered projections (warp / point) -----
__global__ void __launch_bounds__(256) k_attn(const float* __restrict__ x){
    __shared__ float es[8][160];
    __shared__ int   sidx[8][40];
    const int w    = threadIdx.x >> 5;
    const int lane = threadIdx.x & 31;
    const int pg   = blockIdx.x*8 + w;
    const int b    = pg >> 13, p = pg & (NN-1);
    const int* ip  = g_idx + (size_t)pg*KNB;
    sidx[w][lane] = ip[lane];
    if (lane < 8) sidx[w][lane+32] = ip[lane+32];
    const float* qrow = g_qp + (size_t)pg*CC;
    const float* kb   = g_kp + (size_t)b*NN*CC;
    const float* vb   = g_vp + (size_t)b*NN*CC;
    const float q0 = qrow[lane]    * 0.25f;
    const float q1 = qrow[lane+32] * 0.25f;
    const float kn0 = kb[(size_t)p*CC + lane];
    const float kn1 = kb[(size_t)p*CC + lane + 32];
    __syncwarp();
    const int hq = lane >> 4;
    for (int j = 0; j < KNB; j++){
        const float* kr = kb + (size_t)sidx[w][j]*CC;
        float p0 = q0*(kr[lane]    - kn0);
        float p1 = q1*(kr[lane+32] - kn1);
        #pragma unroll
        for (int o = 8; o; o >>= 1){
            p0 += __shfl_xor_sync(0xffffffffu, p0, o);
            p1 += __shfl_xor_sync(0xffffffffu, p1, o);
        }
        if ((lane & 15) == 0){
            es[w][hq*40 + j]     = p0;
            es[w][(2+hq)*40 + j] = p1;
        }
    }
    __syncwarp();
    if (lane < 4){
        float m = -3.4e38f;
        for (int j = 0; j < KNB; j++) m = fmaxf(m, es[w][lane*40+j]);
        float ssum = 0.f;
        for (int j = 0; j < KNB; j++){
            float e = __expf(es[w][lane*40+j] - m);
            es[w][lane*40+j] = e;
            ssum += e;
        }
        float inv = 1.f/ssum;
        for (int j = 0; j < KNB; j++) es[w][lane*40+j] *= inv;
    }
    __syncwarp();
    const float vn0 = vb[(size_t)p*CC + lane];
    const float vn1 = vb[(size_t)p*CC + lane + 32];
    float a0 = 0.f, a1 = 0.f;
    for (int j = 0; j < KNB; j++){
        const float* vr = vb + (size_t)sidx[w][j]*CC;
        a0 += es[w][hq*40+j]     * (vr[lane]    - vn0);
        a1 += es[w][(2+hq)*40+j] * (vr[lane+32] - vn1);
    }
    const float* xb = x + (size_t)b*CC*NN;
    g_y1[(size_t)pg*CC + lane]      = a0 + xb[(size_t)lane*NN + p];
    g_y1[(size_t)pg*CC + lane + 32] = a1 + xb[(size_t)(lane+32)*NN + p];
}

// ---------------- K5: BN stats (deterministic two-stage) ---------------------
__global__ void __launch_bounds__(256) k_stats(int srcsel, int which){
    __shared__ float ssum[256], ssq[256];
    const float* src = srcsel ? g_y2 : g_y1;
    const int t = threadIdx.x;
    const int c = t & 63, rl = t >> 6;
    const int r0 = blockIdx.x*512;
    float s = 0.f, s2 = 0.f;
    for (int r = rl; r < 512; r += 4){
        float v = src[(size_t)(r0+r)*CC + c];
        s += v; s2 += v*v;
    }
    ssum[t] = s; ssq[t] = s2;
    __syncthreads();
    if (t < 64){
        float a = ssum[t]+ssum[t+64]+ssum[t+128]+ssum[t+192];
        float q = ssq [t]+ssq [t+64]+ssq [t+128]+ssq [t+192];
        float* part = g_part + which*8192;
        part[blockIdx.x*128 + t]      = a;
        part[blockIdx.x*128 + 64 + t] = q;
    }
}

__global__ void k_bnfin(int which, const float* __restrict__ gamma,
                        const float* __restrict__ beta){
    const int c = threadIdx.x;
    const float* part = g_part + which*8192;
    float s = 0.f, s2 = 0.f;
    for (int blk = 0; blk < 64; blk++){
        s  += part[blk*128 + c];
        s2 += part[blk*128 + 64 + c];
    }
    const float inv = 1.f/(float)NPTS;
    float m = s*inv;
    float v = s2*inv - m*m;
    float sc = gamma[c]*rsqrtf(v + 1e-5f);
    g_scb[which*128 + c]      = sc;
    g_scb[which*128 + 64 + c] = beta[c] - m*sc;
}

// ---------------- K6: fused FFN (BN1-apply + W1/lrelu + W2 + residual) ------
#define FFN_SMEM ((64*68 + 64*260 + 256*68 + 256*68)*4)
__global__ void __launch_bounds__(256,1) k_ffn(const float* __restrict__ W1,
                                               const float* __restrict__ W2){
    extern __shared__ float s[];
    float* Xs  = s;
    float* W1t = Xs  + 64*68;
    float* Hs  = W1t + 64*260;
    float* W2t = Hs  + 256*68;
    __shared__ float sc1[64], bs1[64];
    const int t  = threadIdx.x;
    const int r0 = blockIdx.x*64;
    if (t < 64){ sc1[t] = g_scb[t]; bs1[t] = g_scb[64+t]; }
    for (int i = t; i < 256*64; i += 256){
        int o = i>>6, c = i&63;
        W1t[c*260 + o] = W1[i];
    }
    for (int i = t; i < 64*256; i += 256){
        int c = i>>8, o = i&255;
        W2t[o*68 + c] = W2[i];
    }
    __syncthreads();
    for (int i = t; i < 64*64; i += 256){
        int r = i>>6, c = i&63;
        Xs[c*68 + r] = g_y1[(size_t)(r0+r)*CC + c]*sc1[c] + bs1[c];
    }
    __syncthreads();
    {
        const int to = t >> 3, tr = t & 7;
        float acc[8][8];
        #pragma unroll
        for (int i=0;i<8;i++)
            #pragma unroll
            for (int j=0;j<8;j++) acc[i][j] = 0.f;
        #pragma unroll 4
        for (int k = 0; k < 64; k++){
            float4 a0 = *(const float4*)&Xs[k*68 + tr*8];
            float4 a1 = *(const float4*)&Xs[k*68 + tr*8 + 4];
            float4 w0 = *(const float4*)&W1t[k*260 + to*8];
            float4 w1 = *(const float4*)&W1t[k*260 + to*8 + 4];
            float av[8] = {a0.x,a0.y,a0.z,a0.w,a1.x,a1.y,a1.z,a1.w};
            float wv[8] = {w0.x,w0.y,w0.z,w0.w,w1.x,w1.y,w1.z,w1.w};
            #pragma unroll
            for (int oi=0;oi<8;oi++)
                #pragma unroll
                for (int ri=0;ri<8;ri++) acc[oi][ri] += wv[oi]*av[ri];
        }
        #pragma unroll
        for (int oi=0;oi<8;oi++)
            #pragma unroll
            for (int ri=0;ri<8;ri++){
                float h = acc[oi][ri];
                Hs[(to*8+oi)*68 + tr*8+ri] = (h > 0.f) ? h : 0.2f*h;
            }
    }
    __syncthreads();
    {
        const int tr2 = t & 15, tc2 = t >> 4;
        float acc[4][4];
        #pragma unroll
        for (int i=0;i<4;i++){ acc[i][0]=0.f; acc[i][1]=0.f; acc[i][2]=0.f; acc[i][3]=0.f; }
        #pragma unroll 8
        for (int o = 0; o < 256; o++){
            float4 h4 = *(const float4*)&Hs[o*68 + tr2*4];
            float4 w4 = *(const float4*)&W2t[o*68 + tc2*4];
            float hv[4] = {h4.x,h4.y,h4.z,h4.w};
            float wv[4] = {w4.x,w4.y,w4.z,w4.w};
            #pragma unroll
            for (int i=0;i<4;i++)
                #pragma unroll
                for (int j=0;j<4;j++) acc[i][j] += hv[i]*wv[j];
        }
        #pragma unroll
        for (int i = 0; i < 4; i++){
            int r = tr2*4 + i;
            float4 outv;
            outv.x = acc[i][0] + Xs[(tc2*4+0)*68 + r];
            outv.y = acc[i][1] + Xs[(tc2*4+1)*68 + r];
            outv.z = acc[i][2] + Xs[(tc2*4+2)*68 + r];
            outv.w = acc[i][3] + Xs[(tc2*4+3)*68 + r];
            *(float4*)&g_y2[(size_t)(r0+r)*CC + tc2*4] = outv;
        }
    }
}

// ---------------- K8: apply BN2 + transpose to (B,C,N) ----------------------
__global__ void __launch_bounds__(256) k_apply(float* __restrict__ out){
    __shared__ float tile[64][65];
    __shared__ float sc[64], bs[64];
    const int t = threadIdx.x;
    if (t < 64){ sc[t] = g_scb[128 + t]; bs[t] = g_scb[128 + 64 + t]; }
    const int n0 = blockIdx.x*64, b = blockIdx.y;
    __syncthreads();
    for (int i = t; i < 64*64; i += 256){
        int r = i>>6, c = i&63;
        tile[c][r] = g_y2[((size_t)b*NN + n0 + r)*CC + c]*sc[c] + bs[c];
    }
    __syncthreads();
    for (int i = t; i < 64*64; i += 256){
        int c = i>>6, n = i&63;
        out[((size_t)b*CC + c)*NN + n0 + n] = tile[c][n];
    }
}

// ---------------- launch -----------------------------------------------------
extern "C" void kernel_launch(void* const* d_in, const int* in_sizes, int n_in,
                              void* d_out, int out_size){
    const float* x  = (const float*)d_in[0];
    const float* Wq = (const float*)d_in[1];
    const float* Wk = (const float*)d_in[2];
    const float* Wv = (const float*)d_in[3];
    const float* W1 = (const float*)d_in[4];
    const float* W2 = (const float*)d_in[5];
    const float* g1 = (const float*)d_in[6];
    const float* b1 = (const float*)d_in[7];
    const float* g2 = (const float*)d_in[8];
    const float* b2 = (const float*)d_in[9];
    float* out = (float*)d_out;
    (void)in_sizes; (void)n_in; (void)out_size;

    cudaFuncSetAttribute(k_knn, cudaFuncAttributeMaxDynamicSharedMemorySize, KNN_SMEM);
    cudaFuncSetAttribute(k_ffn, cudaFuncAttributeMaxDynamicSharedMemorySize, FFN_SMEM);

    k_transpose<<<dim3(NN/32, CC/32, BB), dim3(32, 8)>>>(x);
    k_aa<<<NPTS/8, 256>>>();
    k_split<<<NPTS*CC/256, 256>>>();
    k_proj<<<NPTS/64, 256>>>(Wq, Wk, Wv);
    k_knn<<<dim3(NN/128, BB), 256, KNN_SMEM>>>();
    k_attn<<<NPTS/8, 256>>>(x);
    k_stats<<<64, 256>>>(0, 0);
    k_bnfin<<<1, 64>>>(0, g1, b1);
    k_ffn<<<NPTS/64, 256, FFN_SMEM>>>(W1, W2);
    k_stats<<<64, 256>>>(1, 1);
    k_bnfin<<<1, 64>>>(1, g2, b2);
    k_apply<<<dim3(NN/64, BB), 256>>>(out);
}

// round 9
// speedup vs baseline: 4.3543x; 1.1416x over previous
#include <cuda_runtime.h>
#include <cuda_bf16.h>
#include <cstdint>

#define BB 4
#define CC 64
#define NN 8192
#define KNB 40
#define FFD 256
#define NPTS (BB*NN)
#define BCAP 48
#define BPITCH 49
#define CTILE 128
#define QTILE 64

// ---------------- scratch (device globals: no allocations allowed) ----------
__device__ float g_pcd[NPTS*CC];   // (B,N,C) transposed input
__device__ __nv_bfloat16 g_pch[NPTS*CC]; // bf16 hi split
__device__ __nv_bfloat16 g_pcl[NPTS*CC]; // bf16 lo split
__device__ float g_aa [NPTS];      // squared norms
__device__ float g_qp [NPTS*CC];   // pcd @ Wq^T
__device__ float g_kp [NPTS*CC];   // pcd @ Wk^T
__device__ float g_vp [NPTS*CC];   // pcd @ Wv^T
__device__ int   g_idx[NPTS*KNB];  // knn indices
__device__ float g_y1 [NPTS*CC];
__device__ float g_y2 [NPTS*CC];
__device__ float g_part[2*64*128];
__device__ float g_scb [2*128];

// ---------------- K1: transpose x (B,C,N) -> pcd (B,N,C) --------------------
__global__ void k_transpose(const float* __restrict__ x){
    __shared__ float t[32][33];
    const int n0 = blockIdx.x*32, c0 = blockIdx.y*32, b = blockIdx.z;
    const float* xb = x + (size_t)b*CC*NN;
    #pragma unroll
    for (int i = threadIdx.y; i < 32; i += 8)
        t[i][threadIdx.x] = xb[(size_t)(c0+i)*NN + n0 + threadIdx.x];
    __syncthreads();
    float* pb = g_pcd + (size_t)b*NN*CC;
    #pragma unroll
    for (int i = threadIdx.y; i < 32; i += 8)
        pb[(size_t)(n0+i)*CC + c0 + threadIdx.x] = t[threadIdx.x][i];
}

// ---------------- K1b: aa + bf16 hi/lo split ---------------------------------
__global__ void k_aa(){
    const int p    = blockIdx.x*8 + (threadIdx.x>>5);
    const int lane = threadIdx.x & 31;
    const float* r = g_pcd + (size_t)p*CC;
    float a = r[lane]*r[lane] + r[lane+32]*r[lane+32];
    #pragma unroll
    for (int o = 16; o; o >>= 1) a += __shfl_xor_sync(0xffffffffu, a, o);
    if (!lane) g_aa[p] = a;
}
__global__ void k_split(){
    const int i = blockIdx.x*256 + threadIdx.x;
    float v = g_pcd[i];
    __nv_bfloat16 h = __float2bfloat16(v);
    g_pch[i] = h;
    g_pcl[i] = __float2bfloat16(v - __bfloat162float(h));
}

// ---------------- K2: qp/kp/vp = pcd @ W^T (64-pt tiles) ---------------------
__global__ void __launch_bounds__(256) k_proj(const float* __restrict__ Wq,
                                              const float* __restrict__ Wk,
                                              const float* __restrict__ Wv){
    __shared__ float Pt[64*68];   // [k][p]
    __shared__ float Wt[64*68];   // [k][o]
    const int t  = threadIdx.x;
    const int r0 = blockIdx.x*64;
    for (int i = t; i < 64*64; i += 256){
        int p = i>>6, k = i&63;
        Pt[k*68+p] = g_pcd[(size_t)(r0+p)*CC + k];
    }
    const int tp = t & 15, to = t >> 4;
    const float* Ws[3] = {Wq, Wk, Wv};
    float* Os[3];
    Os[0] = g_qp; Os[1] = g_kp; Os[2] = g_vp;
    for (int m = 0; m < 3; m++){
        __syncthreads();
        const float* W = Ws[m];
        for (int i = t; i < 64*64; i += 256){
            int o = i>>6, k = i&63;
            Wt[k*68+o] = W[i];
        }
        __syncthreads();
        float acc[4][4];
        #pragma unroll
        for (int i=0;i<4;i++) { acc[i][0]=0.f; acc[i][1]=0.f; acc[i][2]=0.f; acc[i][3]=0.f; }
        #pragma unroll 8
        for (int kk = 0; kk < 64; kk++){
            float4 a = *(const float4*)&Pt[kk*68 + tp*4];
            float4 w = *(const float4*)&Wt[kk*68 + to*4];
            float av[4] = {a.x,a.y,a.z,a.w};
            float wv[4] = {w.x,w.y,w.z,w.w};
            #pragma unroll
            for (int i=0;i<4;i++)
                #pragma unroll
                for (int j=0;j<4;j++) acc[i][j] += av[i]*wv[j];
        }
        float* O = Os[m];
        #pragma unroll
        for (int i = 0; i < 4; i++){
            float4 v4 = make_float4(acc[i][0], acc[i][1], acc[i][2], acc[i][3]);
            *(float4*)&O[(size_t)(r0 + tp*4 + i)*CC + to*4] = v4;
        }
    }
}

// ---------------- K3: KNN via mma.sync bf16-split GEMM + filtered top-40 ----
// 64 queries/block, 2 blocks/SM. smem bytes:
//   QH@0 9216 | QL@9216 | CH@18432 18432 | CL@36864 | fx @55296
#define PITCHB 144            // 72 bf16 per row
#define QH_OFF 0
#define QL_OFF 9216
#define CH_OFF 18432
#define CL_OFF 36864
#define FX_OFF 55296
// fx floats: aq 64 | ac 128 | thr 64 | ld 40*64 | bufv 64*49 | li 40*64 |
//            bufi 64*49 | cnt 64 | redo
#define KNN_SMEM (FX_OFF + 11716*4)

#define MMA_BF16(dd, a, b0_, b1_) \
    asm volatile("mma.sync.aligned.m16n8k16.row.col.f32.bf16.bf16.f32 " \
        "{%0,%1,%2,%3}, {%4,%5,%6,%7}, {%8,%9}, {%0,%1,%2,%3};" \
        : "+f"((dd)[0]), "+f"((dd)[1]), "+f"((dd)[2]), "+f"((dd)[3]) \
        : "r"((a)[0]), "r"((a)[1]), "r"((a)[2]), "r"((a)[3]), \
          "r"(b0_), "r"(b1_))

__global__ void __launch_bounds__(256,2) k_knn(){
    extern __shared__ char sm[];
    float* fx   = (float*)(sm + FX_OFF);
    float* aq   = fx;                  // 64
    float* ac   = fx + 64;             // 128
    float* thr  = fx + 192;            // 64
    float* ld   = fx + 256;            // 40*64
    float* bufv = fx + 2816;           // 64*49
    int*   li   = (int*)(fx + 5952);   // 40*64
    int*   bufi = (int*)(fx + 8512);   // 64*49
    int*   cnt  = (int*)(fx + 11648);  // 64
    int*   s_redo = (int*)(fx + 11712);

    const int b  = blockIdx.y;
    const int q0 = blockIdx.x*QTILE;
    const int t  = threadIdx.x;
    const int wid  = t >> 5;
    const int lane = t & 31;
    const int g  = lane >> 2;          // group row 0..7
    const int qq = lane & 3;           // quad col 0..3
    const int qb = (wid & 3)*16;       // warp's query base (row within tile)
    const int cb = (wid >> 2)*64;      // warp's candidate-col base

    // ---- stage Q tiles (bf16 hi/lo) ----
    {
        const uint4* qh = (const uint4*)(g_pch + (size_t)(b*NN + q0)*CC);
        const uint4* ql = (const uint4*)(g_pcl + (size_t)(b*NN + q0)*CC);
        for (int i = t; i < QTILE*8; i += 256){
            int row = i >> 3, c16 = i & 7;
            int off = row*PITCHB + c16*16;
            *(uint4*)(sm + QH_OFF + off) = qh[i];
            *(uint4*)(sm + QL_OFF + off) = ql[i];
        }
    }
    if (t < QTILE){ aq[t] = g_aa[(size_t)b*NN + q0 + t]; thr[t] = -3.4e38f; cnt[t] = 0; }

    float vmin = -3.4e38f;   // owner state (t<64 owns query t)
    int   minpos = 0;

    for (int ct = 0; ct < NN/CTILE; ct++){
        __syncthreads();   // previous tile fully consumed
        const int c0 = ct*CTILE;

        // ---- stage C tiles (bf16 hi/lo) + ac ----
        {
            const uint4* ch = (const uint4*)(g_pch + (size_t)(b*NN + c0)*CC);
            const uint4* cl = (const uint4*)(g_pcl + (size_t)(b*NN + c0)*CC);
            for (int i = t; i < CTILE*8; i += 256){
                int row = i >> 3, c16 = i & 7;
                int off = row*PITCHB + c16*16;
                *(uint4*)(sm + CH_OFF + off) = ch[i];
                *(uint4*)(sm + CL_OFF + off) = cl[i];
            }
            if (t < 128) ac[t] = g_aa[(size_t)b*NN + c0 + t];
        }
        __syncthreads();

        // ---- warp GEMM: 16q x 64c via m16n8k16, 3-term bf16 split ----
        float d[8][4];
        #pragma unroll
        for (int ni=0;ni<8;ni++)
            #pragma unroll
            for (int j=0;j<4;j++) d[ni][j] = 0.f;

        #pragma unroll
        for (int kc = 0; kc < 4; kc++){
            const int koff = kc*32 + qq*4;   // bytes within row
            uint32_t ah[4], al[4];
            {
                int r0b = (qb + g)*PITCHB + koff;
                int r1b = r0b + 8*PITCHB;
                ah[0] = *(const uint32_t*)(sm + QH_OFF + r0b);
                ah[1] = *(const uint32_t*)(sm + QH_OFF + r1b);
                ah[2] = *(const uint32_t*)(sm + QH_OFF + r0b + 16);
                ah[3] = *(const uint32_t*)(sm + QH_OFF + r1b + 16);
                al[0] = *(const uint32_t*)(sm + QL_OFF + r0b);
                al[1] = *(const uint32_t*)(sm + QL_OFF + r1b);
                al[2] = *(const uint32_t*)(sm + QL_OFF + r0b + 16);
                al[3] = *(const uint32_t*)(sm + QL_OFF + r1b + 16);
            }
            #pragma unroll
            for (int ni=0;ni<8;ni++){
                int crb = (cb + ni*8 + g)*PITCHB + koff;
                uint32_t bh0 = *(const uint32_t*)(sm + CH_OFF + crb);
                uint32_t bh1 = *(const uint32_t*)(sm + CH_OFF + crb + 16);
                uint32_t bl0 = *(const uint32_t*)(sm + CL_OFF + crb);
                uint32_t bl1 = *(const uint32_t*)(sm + CL_OFF + crb + 16);
                MMA_BF16(d[ni], ah, bh0, bh1);
                MMA_BF16(d[ni], ah, bl0, bl1);
                MMA_BF16(d[ni], al, bh0, bh1);
            }
        }

        // ---- fold pd = 2*dot - aq - ac into fragments ----
        {
            float aq0 = aq[qb + g];
            float aq1 = aq[qb + g + 8];
            #pragma unroll
            for (int ni=0;ni<8;ni++){
                float ac0 = ac[cb + ni*8 + qq*2];
                float ac1 = ac[cb + ni*8 + qq*2 + 1];
                d[ni][0] = 2.f*d[ni][0] - aq0 - ac0;
                d[ni][1] = 2.f*d[ni][1] - aq0 - ac1;
                d[ni][2] = 2.f*d[ni][2] - aq1 - ac0;
                d[ni][3] = 2.f*d[ni][3] - aq1 - ac1;
            }
        }

        unsigned pend = 0xFFFFFFFFu;   // 8 ni x 4 j

        if (ct == 0){
            // direct-init: cols 0..39 (ni<5 in cb==0 warps) fill slots directly
            if (cb == 0){
                #pragma unroll
                for (int ni=0;ni<5;ni++){
                    #pragma unroll
                    for (int j=0;j<4;j++){
                        int col = ni*8 + qq*2 + (j&1);
                        int row = qb + g + ((j>>1)<<3);
                        ld[col*QTILE + row] = d[ni][j];
                        li[col*QTILE + row] = col;
                    }
                }
                pend &= 0xFFF00000u;   // clear ni 0..4
            }
            __syncthreads();
            if (t < QTILE){
                vmin = 3.4e38f;
                #pragma unroll
                for (int j = 0; j < KNB; j++){
                    float lv = ld[j*QTILE + t];
                    if (lv < vmin){ vmin = lv; minpos = j; }
                }
                thr[t] = vmin;
            }
        }

        // ---- filter / insert retry loop ----
        for (;;){
            if (t == 0) s_redo[0] = 0;
            __syncthreads();
            if (pend){
                const int r0w = qb + g;
                const float th0 = thr[r0w], th1 = thr[r0w + 8];
                #pragma unroll
                for (int ni=0;ni<8;ni++){
                    #pragma unroll
                    for (int j=0;j<4;j++){
                        const unsigned bit = 1u << (ni*4 + j);
                        if (!(pend & bit)) continue;
                        float v = d[ni][j];
                        int row = r0w + ((j>>1)<<3);
                        float th = (j>>1) ? th1 : th0;
                        if (v <= th){ pend &= ~bit; continue; }
                        int pos = atomicAdd(&cnt[row], 1);
                        if (pos < BCAP){
                            bufv[row*BPITCH + pos] = v;
                            bufi[row*BPITCH + pos] = c0 + cb + ni*8 + qq*2 + (j&1);
                            pend &= ~bit;
                        } else s_redo[0] = 1;
                    }
                }
            }
            __syncthreads();
            if (t < QTILE){
                int n = cnt[t]; if (n > BCAP) n = BCAP;
                for (int s2 = 0; s2 < n; s2++){
                    float v = bufv[t*BPITCH + s2];
                    if (v > vmin){
                        ld[minpos*QTILE + t] = v;
                        li[minpos*QTILE + t] = bufi[t*BPITCH + s2];
                        vmin = 3.4e38f;
                        #pragma unroll
                        for (int j = 0; j < KNB; j++){
                            float lv = ld[j*QTILE + t];
                            if (lv < vmin){ vmin = lv; minpos = j; }
                        }
                    }
                }
                cnt[t] = 0;
                thr[t] = vmin;
            }
            int r = s_redo[0];
            __syncthreads();
            if (!r) break;
        }
    }

    __syncthreads();
    if (t < QTILE){
        int* dst = g_idx + ((size_t)b*NN + q0 + t)*KNB;
        #pragma unroll
        for (int j = 0; j < KNB; j++) dst[j] = li[j*QTILE + t];
    }
}

// ---------------- K4: attention via gathered projections (warp / point) -----
__global__ void __launch_bounds__(256) k_attn(const float* __restrict__ x){
    __shared__ float es[8][160];
    __shared__ int   sidx[8][40];
    const int w    = threadIdx.x >> 5;
    const int lane = threadIdx.x & 31;
    const int pg   = blockIdx.x*8 + w;
    const int b    = pg >> 13, p = pg & (NN-1);
    const int* ip  = g_idx + (size_t)pg*KNB;
    sidx[w][lane] = ip[lane];
    if (lane < 8) sidx[w][lane+32] = ip[lane+32];
    const float* qrow = g_qp + (size_t)pg*CC;
    const float* kb   = g_kp + (size_t)b*NN*CC;
    const float* vb   = g_vp + (size_t)b*NN*CC;
    const float q0 = qrow[lane]    * 0.25f;
    const float q1 = qrow[lane+32] * 0.25f;
    const float kn0 = kb[(size_t)p*CC + lane];
    const float kn1 = kb[(size_t)p*CC + lane + 32];
    __syncwarp();
    const int hq = lane >> 4;
    for (int j = 0; j < KNB; j++){
        const float* kr = kb + (size_t)sidx[w][j]*CC;
        float p0 = q0*(kr[lane]    - kn0);
        float p1 = q1*(kr[lane+32] - kn1);
        #pragma unroll
        for (int o = 8; o; o >>= 1){
            p0 += __shfl_xor_sync(0xffffffffu, p0, o);
            p1 += __shfl_xor_sync(0xffffffffu, p1, o);
        }
        if ((lane & 15) == 0){
            es[w][hq*40 + j]     = p0;
            es[w][(2+hq)*40 + j] = p1;
        }
    }
    __syncwarp();
    if (lane < 4){
        float m = -3.4e38f;
        for (int j = 0; j < KNB; j++) m = fmaxf(m, es[w][lane*40+j]);
        float ssum = 0.f;
        for (int j = 0; j < KNB; j++){
            float e = __expf(es[w][lane*40+j] - m);
            es[w][lane*40+j] = e;
            ssum += e;
        }
        float inv = 1.f/ssum;
        for (int j = 0; j < KNB; j++) es[w][lane*40+j] *= inv;
    }
    __syncwarp();
    const float vn0 = vb[(size_t)p*CC + lane];
    const float vn1 = vb[(size_t)p*CC + lane + 32];
    float a0 = 0.f, a1 = 0.f;
    for (int j = 0; j < KNB; j++){
        const float* vr = vb + (size_t)sidx[w][j]*CC;
        a0 += es[w][hq*40+j]     * (vr[lane]    - vn0);
        a1 += es[w][(2+hq)*40+j] * (vr[lane+32] - vn1);
    }
    const float* xb = x + (size_t)b*CC*NN;
    g_y1[(size_t)pg*CC + lane]      = a0 + xb[(size_t)lane*NN + p];
    g_y1[(size_t)pg*CC + lane + 32] = a1 + xb[(size_t)(lane+32)*NN + p];
}

// ---------------- K5: BN stats (deterministic two-stage) ---------------------
__global__ void __launch_bounds__(256) k_stats(int srcsel, int which){
    __shared__ float ssum[256], ssq[256];
    const float* src = srcsel ? g_y2 : g_y1;
    const int t = threadIdx.x;
    const int c = t & 63, rl = t >> 6;
    const int r0 = blockIdx.x*512;
    float s = 0.f, s2 = 0.f;
    for (int r = rl; r < 512; r += 4){
        float v = src[(size_t)(r0+r)*CC + c];
        s += v; s2 += v*v;
    }
    ssum[t] = s; ssq[t] = s2;
    __syncthreads();
    if (t < 64){
        float a = ssum[t]+ssum[t+64]+ssum[t+128]+ssum[t+192];
        float q = ssq [t]+ssq [t+64]+ssq [t+128]+ssq [t+192];
        float* part = g_part + which*8192;
        part[blockIdx.x*128 + t]      = a;
        part[blockIdx.x*128 + 64 + t] = q;
    }
}

__global__ void k_bnfin(int which, const float* __restrict__ gamma,
                        const float* __restrict__ beta){
    const int c = threadIdx.x;
    const float* part = g_part + which*8192;
    float s = 0.f, s2 = 0.f;
    for (int blk = 0; blk < 64; blk++){
        s  += part[blk*128 + c];
        s2 += part[blk*128 + 64 + c];
    }
    const float inv = 1.f/(float)NPTS;
    float m = s*inv;
    float v = s2*inv - m*m;
    float sc = gamma[c]*rsqrtf(v + 1e-5f);
    g_scb[which*128 + c]      = sc;
    g_scb[which*128 + 64 + c] = beta[c] - m*sc;
}

// ---------------- K6: fused FFN (BN1-apply + W1/lrelu + W2 + residual) ------
#define FFN_SMEM ((64*68 + 64*260 + 256*68 + 256*68)*4)
__global__ void __launch_bounds__(256,1) k_ffn(const float* __restrict__ W1,
                                               const float* __restrict__ W2){
    extern __shared__ float s[];
    float* Xs  = s;
    float* W1t = Xs  + 64*68;
    float* Hs  = W1t + 64*260;
    float* W2t = Hs  + 256*68;
    __shared__ float sc1[64], bs1[64];
    const int t  = threadIdx.x;
    const int r0 = blockIdx.x*64;
    if (t < 64){ sc1[t] = g_scb[t]; bs1[t] = g_scb[64+t]; }
    for (int i = t; i < 256*64; i += 256){
        int o = i>>6, c = i&63;
        W1t[c*260 + o] = W1[i];
    }
    for (int i = t; i < 64*256; i += 256){
        int c = i>>8, o = i&255;
        W2t[o*68 + c] = W2[i];
    }
    __syncthreads();
    for (int i = t; i < 64*64; i += 256){
        int r = i>>6, c = i&63;
        Xs[c*68 + r] = g_y1[(size_t)(r0+r)*CC + c]*sc1[c] + bs1[c];
    }
    __syncthreads();
    {
        const int to = t >> 3, tr = t & 7;
        float acc[8][8];
        #pragma unroll
        for (int i=0;i<8;i++)
            #pragma unroll
            for (int j=0;j<8;j++) acc[i][j] = 0.f;
        #pragma unroll 4
        for (int k = 0; k < 64; k++){
            float4 a0 = *(const float4*)&Xs[k*68 + tr*8];
            float4 a1 = *(const float4*)&Xs[k*68 + tr*8 + 4];
            float4 w0 = *(const float4*)&W1t[k*260 + to*8];
            float4 w1 = *(const float4*)&W1t[k*260 + to*8 + 4];
            float av[8] = {a0.x,a0.y,a0.z,a0.w,a1.x,a1.y,a1.z,a1.w};
            float wv[8] = {w0.x,w0.y,w0.z,w0.w,w1.x,w1.y,w1.z,w1.w};
            #pragma unroll
            for (int oi=0;oi<8;oi++)
                #pragma unroll
                for (int ri=0;ri<8;ri++) acc[oi][ri] += wv[oi]*av[ri];
        }
        #pragma unroll
        for (int oi=0;oi<8;oi++)
            #pragma unroll
            for (int ri=0;ri<8;ri++){
                float h = acc[oi][ri];
                Hs[(to*8+oi)*68 + tr*8+ri] = (h > 0.f) ? h : 0.2f*h;
            }
    }
    __syncthreads();
    {
        const int tr2 = t & 15, tc2 = t >> 4;
        float acc[4][4];
        #pragma unroll
        for (int i=0;i<4;i++){ acc[i][0]=0.f; acc[i][1]=0.f; acc[i][2]=0.f; acc[i][3]=0.f; }
        #pragma unroll 8
        for (int o = 0; o < 256; o++){
            float4 h4 = *(const float4*)&Hs[o*68 + tr2*4];
            float4 w4 = *(const float4*)&W2t[o*68 + tc2*4];
            float hv[4] = {h4.x,h4.y,h4.z,h4.w};
            float wv[4] = {w4.x,w4.y,w4.z,w4.w};
            #pragma unroll
            for (int i=0;i<4;i++)
                #pragma unroll
                for (int j=0;j<4;j++) acc[i][j] += hv[i]*wv[j];
        }
        #pragma unroll
        for (int i = 0; i < 4; i++){
            int r = tr2*4 + i;
            float4 outv;
            outv.x = acc[i][0] + Xs[(tc2*4+0)*68 + r];
            outv.y = acc[i][1] + Xs[(tc2*4+1)*68 + r];
            outv.z = acc[i][2] + Xs[(tc2*4+2)*68 + r];
            outv.w = acc[i][3] + Xs[(tc2*4+3)*68 + r];
            *(float4*)&g_y2[(size_t)(r0+r)*CC + tc2*4] = outv;
        }
    }
}

// ---------------- K8: apply BN2 + transpose to (B,C,N) ----------------------
__global__ void __launch_bounds__(256) k_apply(float* __restrict__ out){
    __shared__ float tile[64][65];
    __shared__ float sc[64], bs[64];
    const int t = threadIdx.x;
    if (t < 64){ sc[t] = g_scb[128 + t]; bs[t] = g_scb[128 + 64 + t]; }
    const int n0 = blockIdx.x*64, b = blockIdx.y;
    __syncthreads();
    for (int i = t; i < 64*64; i += 256){
        int r = i>>6, c = i&63;
        tile[c][r] = g_y2[((size_t)b*NN + n0 + r)*CC + c]*sc[c] + bs[c];
    }
    __syncthreads();
    for (int i = t; i < 64*64; i += 256){
        int c = i>>6, n = i&63;
        out[((size_t)b*CC + c)*NN + n0 + n] = tile[c][n];
    }
}

// ---------------- launch -----------------------------------------------------
extern "C" void kernel_launch(void* const* d_in, const int* in_sizes, int n_in,
                              void* d_out, int out_size){
    const float* x  = (const float*)d_in[0];
    const float* Wq = (const float*)d_in[1];
    const float* Wk = (const float*)d_in[2];
    const float* Wv = (const float*)d_in[3];
    const float* W1 = (const float*)d_in[4];
    const float* W2 = (const float*)d_in[5];
    const float* g1 = (const float*)d_in[6];
    const float* b1 = (const float*)d_in[7];
    const float* g2 = (const float*)d_in[8];
    const float* b2 = (const float*)d_in[9];
    float* out = (float*)d_out;
    (void)in_sizes; (void)n_in; (void)out_size;

    cudaFuncSetAttribute(k_knn, cudaFuncAttributeMaxDynamicSharedMemorySize, KNN_SMEM);
    cudaFuncSetAttribute(k_ffn, cudaFuncAttributeMaxDynamicSharedMemorySize, FFN_SMEM);

    k_transpose<<<dim3(NN/32, CC/32, BB), dim3(32, 8)>>>(x);
    k_aa<<<NPTS/8, 256>>>();
    k_split<<<NPTS*CC/256, 256>>>();
    k_proj<<<NPTS/64, 256>>>(Wq, Wk, Wv);
    k_knn<<<dim3(NN/QTILE, BB), 256, KNN_SMEM>>>();
    k_attn<<<NPTS/8, 256>>>(x);
    k_stats<<<64, 256>>>(0, 0);
    k_bnfin<<<1, 64>>>(0, g1, b1);
    k_ffn<<<NPTS/64, 256, FFN_SMEM>>>(W1, W2);
    k_stats<<<64, 256>>>(1, 1);
    k_bnfin<<<1, 64>>>(1, g2, b2);
    k_apply<<<dim3(NN/64, BB), 256>>>(out);
}